// round 8
// baseline (speedup 1.0000x reference)
#include <cuda_runtime.h>
#include <math.h>
#include <stdint.h>

// ---------------- dims ----------------
#define LL   2048
#define DD   1024
#define II   2048
#define NST  16
#define TSRD 64
#define HQ   16
#define NCH  32
#define CHSZ 64
#define EPSV 1e-6f

// ---------------- scratch ----------------
__device__ float g_proj [LL * 2 * II];
__device__ float g_klin [LL * 512];
__device__ float g_vlin [LL * 512];
__device__ float g_ucl  [LL * II];
__device__ float g_ssm  [LL * 96];
__device__ float g_dtn  [LL * TSRD];
__device__ float g_Bn   [LL * NST];
__device__ float g_Cn   [LL * NST];
__device__ float g_dtact[LL * II];
__device__ float g_chunkh[NCH * II * NST];
__device__ float g_sumdt [NCH * II];
__device__ float g_hstart[NCH * II * NST];
__device__ float g_mamba[LL * II];
__device__ float g_qr   [LL * II];
__device__ float g_kr   [LL * 512];
__device__ float g_attn [LL * II];
__device__ float g_fused[LL * II];

// ---------------- TF32 helpers ----------------
__device__ __forceinline__ uint32_t f2tf(float x) {
    uint32_t r;
    asm("cvt.rna.tf32.f32 %0, %1;" : "=r"(r) : "f"(x));
    return r;
}
__device__ __forceinline__ void mma_tf32(float* c,
    uint32_t a0, uint32_t a1, uint32_t a2, uint32_t a3,
    uint32_t b0, uint32_t b1)
{
    asm volatile(
        "mma.sync.aligned.m16n8k8.row.col.f32.tf32.tf32.f32 "
        "{%0,%1,%2,%3}, {%4,%5,%6,%7}, {%8,%9}, {%0,%1,%2,%3};"
        : "+f"(c[0]), "+f"(c[1]), "+f"(c[2]), "+f"(c[3])
        : "r"(a0), "r"(a1), "r"(a2), "r"(a3), "r"(b0), "r"(b1));
}

// ---------------- TF32 tensor-core GEMM: 128x128 tile, BK=16, 8 warps x (64x32) ----------------
// nsplit>1: blockIdx.z = K-split; partials atomicAdd'ed into pre-zeroed C.
__global__ __launch_bounds__(256) void gemm_tc(
    const float* __restrict__ A, const float* __restrict__ B, float* __restrict__ C,
    int M, int N, int K, const float* __restrict__ bias, int act, int nsplit)
{
    __shared__ uint32_t As[16][136];
    __shared__ uint32_t Bs[16][136];
    const int tid = threadIdx.x;
    const int m0 = blockIdx.y * 128;
    const int n0 = blockIdx.x * 128;
    const int klen = K / nsplit;
    const int ks = blockIdx.z * klen;
    const int warp = tid >> 5, lane = tid & 31;
    const int wm = (warp >> 2) * 64;      // warp M base within tile
    const int wn = (warp & 3) * 32;       // warp N base within tile
    const int grp = lane >> 2, qid = lane & 3;

    float acc[4][4][4];
#pragma unroll
    for (int mi = 0; mi < 4; mi++)
#pragma unroll
        for (int ni = 0; ni < 4; ni++)
#pragma unroll
            for (int r = 0; r < 4; r++) acc[mi][ni][r] = 0.f;

    const int la_m = tid >> 1;            // 0..127
    const int la_k = (tid & 1) * 8;       // 0 or 8
    const int lb_r = tid >> 4;            // 0..15 (k row)
    const int lb_c = (tid & 15) * 8;      // 0..120 (n col)

    for (int k0 = ks; k0 < ks + klen; k0 += 16) {
        // A tile: 128 x 16
        {
            const float* ap = A + (size_t)(m0 + la_m) * K + k0 + la_k;
            float4 v0 = *(const float4*)(ap);
            float4 v1 = *(const float4*)(ap + 4);
            As[la_k + 0][la_m] = f2tf(v0.x);
            As[la_k + 1][la_m] = f2tf(v0.y);
            As[la_k + 2][la_m] = f2tf(v0.z);
            As[la_k + 3][la_m] = f2tf(v0.w);
            As[la_k + 4][la_m] = f2tf(v1.x);
            As[la_k + 5][la_m] = f2tf(v1.y);
            As[la_k + 6][la_m] = f2tf(v1.z);
            As[la_k + 7][la_m] = f2tf(v1.w);
        }
        // B tile: 16 x 128
        {
            const float* bp = B + (size_t)(k0 + lb_r) * N;
            int gn = n0 + lb_c;
            if (gn + 7 < N) {
                float4 v0 = *(const float4*)(bp + gn);
                float4 v1 = *(const float4*)(bp + gn + 4);
                Bs[lb_r][lb_c + 0] = f2tf(v0.x);
                Bs[lb_r][lb_c + 1] = f2tf(v0.y);
                Bs[lb_r][lb_c + 2] = f2tf(v0.z);
                Bs[lb_r][lb_c + 3] = f2tf(v0.w);
                Bs[lb_r][lb_c + 4] = f2tf(v1.x);
                Bs[lb_r][lb_c + 5] = f2tf(v1.y);
                Bs[lb_r][lb_c + 6] = f2tf(v1.z);
                Bs[lb_r][lb_c + 7] = f2tf(v1.w);
            } else {
#pragma unroll
                for (int j = 0; j < 8; j++)
                    Bs[lb_r][lb_c + j] = (gn + j < N) ? f2tf(bp[gn + j]) : 0u;
            }
        }
        __syncthreads();

#pragma unroll
        for (int kk = 0; kk < 16; kk += 8) {
            uint32_t af[4][4], bf[4][2];
#pragma unroll
            for (int mi = 0; mi < 4; mi++) {
                int m = wm + mi * 16 + grp;
                af[mi][0] = As[kk + qid][m];
                af[mi][1] = As[kk + qid][m + 8];
                af[mi][2] = As[kk + 4 + qid][m];
                af[mi][3] = As[kk + 4 + qid][m + 8];
            }
#pragma unroll
            for (int ni = 0; ni < 4; ni++) {
                int n = wn + ni * 8 + grp;
                bf[ni][0] = Bs[kk + qid][n];
                bf[ni][1] = Bs[kk + 4 + qid][n];
            }
#pragma unroll
            for (int mi = 0; mi < 4; mi++)
#pragma unroll
                for (int ni = 0; ni < 4; ni++)
                    mma_tf32(acc[mi][ni], af[mi][0], af[mi][1], af[mi][2], af[mi][3],
                             bf[ni][0], bf[ni][1]);
        }
        __syncthreads();
    }

    // epilogue: c0,c1 -> (row grp, cols 2q,2q+1); c2,c3 -> (row grp+8)
#pragma unroll
    for (int mi = 0; mi < 4; mi++) {
#pragma unroll
        for (int ni = 0; ni < 4; ni++) {
            int r0 = m0 + wm + mi * 16 + grp;
            int c0 = n0 + wn + ni * 8 + qid * 2;
#pragma unroll
            for (int half = 0; half < 2; half++) {
                int row = r0 + half * 8;
#pragma unroll
                for (int e = 0; e < 2; e++) {
                    int col = c0 + e;
                    if (col >= N) continue;
                    float v = acc[mi][ni][half * 2 + e];
                    if (nsplit > 1) {
                        atomicAdd(&C[(size_t)row * N + col], v);
                    } else {
                        if (act == 1) {
                            float xx = v + bias[col];
                            v = fmaxf(xx, 0.f) + log1pf(__expf(-fabsf(xx)));
                        }
                        C[(size_t)row * N + col] = v;
                    }
                }
            }
        }
    }
}

// ---------------- conv K=4 + SiLU ----------------
__global__ __launch_bounds__(256) void conv_silu_k(
    const float* __restrict__ proj, const float* __restrict__ cw,
    const float* __restrict__ cb, float* __restrict__ ucl)
{
    int idx = blockIdx.x * 256 + threadIdx.x;
    int t = idx >> 11, i = idx & 2047;
    float4 w = *(const float4*)(cw + i * 4);
    float acc = cb[i];
    if (t >= 3) acc += proj[(size_t)(t - 3) * 4096 + i] * w.x;
    if (t >= 2) acc += proj[(size_t)(t - 2) * 4096 + i] * w.y;
    if (t >= 1) acc += proj[(size_t)(t - 1) * 4096 + i] * w.z;
    acc += proj[(size_t)t * 4096 + i] * w.w;
    ucl[idx] = acc / (1.f + __expf(-acc));
}

// ---------------- rmsnorm dt/B/C ----------------
__global__ __launch_bounds__(128) void rmsnorm_dtbc_k(
    const float* __restrict__ ssm, const float* __restrict__ wdt,
    const float* __restrict__ wB, const float* __restrict__ wC,
    float* __restrict__ dtn, float* __restrict__ Bn, float* __restrict__ Cn)
{
    int warp = (blockIdx.x * blockDim.x + threadIdx.x) >> 5;
    int lane = threadIdx.x & 31;
    if (warp >= LL) return;
    const float* row = ssm + (size_t)warp * 96;

    float v0 = row[lane], v1 = row[lane + 32];
    float ss = v0 * v0 + v1 * v1;
#pragma unroll
    for (int o = 16; o; o >>= 1) ss += __shfl_xor_sync(~0u, ss, o);
    float r = rsqrtf(ss / 64.f + EPSV);
    dtn[warp * 64 + lane]      = v0 * r * wdt[lane];
    dtn[warp * 64 + lane + 32] = v1 * r * wdt[lane + 32];

    float b = (lane < 16) ? row[64 + lane] : 0.f;
    float sb = b * b;
#pragma unroll
    for (int o = 16; o; o >>= 1) sb += __shfl_xor_sync(~0u, sb, o);
    float rb = rsqrtf(sb / 16.f + EPSV);
    if (lane < 16) Bn[warp * 16 + lane] = b * rb * wB[lane];

    float c = (lane < 16) ? row[80 + lane] : 0.f;
    float sc = c * c;
#pragma unroll
    for (int o = 16; o; o >>= 1) sc += __shfl_xor_sync(~0u, sc, o);
    float rc = rsqrtf(sc / 16.f + EPSV);
    if (lane < 16) Cn[warp * 16 + lane] = c * rc * wC[lane];
}

// ---------------- scan pass A ----------------
__global__ __launch_bounds__(128) void scan_passA_k(
    const float* __restrict__ dtact, const float* __restrict__ ucl,
    const float* __restrict__ Bn, const float* __restrict__ A_log,
    float* __restrict__ chunkh, float* __restrict__ sumdt)
{
    __shared__ float Bs[CHSZ][NST];
    const int c = blockIdx.y;
    const int i = blockIdx.x * 128 + threadIdx.x;
    for (int idx = threadIdx.x; idx < CHSZ * NST; idx += 128)
        Bs[idx >> 4][idx & 15] = Bn[(size_t)(c * CHSZ + (idx >> 4)) * NST + (idx & 15)];
    __syncthreads();

    float Ai[NST];
#pragma unroll
    for (int n = 0; n < NST; n++) Ai[n] = -__expf(A_log[(size_t)i * NST + n]);
    bool geom = true;
#pragma unroll
    for (int n = 1; n < NST; n++) {
        float ex = Ai[0] * (float)(n + 1);
        if (fabsf(Ai[n] - ex) > 1e-3f * fabsf(ex)) geom = false;
    }

    float h[NST];
#pragma unroll
    for (int n = 0; n < NST; n++) h[n] = 0.f;
    float sdt = 0.f;

    if (geom) {
        const float a0 = Ai[0];
        for (int t = 0; t < CHSZ; t++) {
            int tg = c * CHSZ + t;
            float dtv = dtact[(size_t)tg * II + i];
            float uv  = ucl[(size_t)tg * II + i];
            sdt += dtv;
            float du = dtv * uv;
            float e1 = __expf(dtv * a0);
            float p = e1;
#pragma unroll
            for (int n = 0; n < NST; n++) {
                h[n] = h[n] * p + du * Bs[t][n];
                p *= e1;
            }
        }
    } else {
        for (int t = 0; t < CHSZ; t++) {
            int tg = c * CHSZ + t;
            float dtv = dtact[(size_t)tg * II + i];
            float uv  = ucl[(size_t)tg * II + i];
            sdt += dtv;
            float du = dtv * uv;
#pragma unroll
            for (int n = 0; n < NST; n++)
                h[n] = h[n] * __expf(dtv * Ai[n]) + du * Bs[t][n];
        }
    }
#pragma unroll
    for (int n = 0; n < NST; n++)
        chunkh[((size_t)c * II + i) * NST + n] = h[n];
    sumdt[c * II + i] = sdt;
}

// ---------------- scan pass B ----------------
__global__ __launch_bounds__(256) void scan_passB_k(
    const float* __restrict__ chunkh, const float* __restrict__ sumdt,
    const float* __restrict__ A_log, float* __restrict__ hstart)
{
    int idx = blockIdx.x * 256 + threadIdx.x;
    int i = idx >> 4;
    float A = -__expf(A_log[idx]);
    float h = 0.f;
    for (int c = 0; c < NCH; c++) {
        hstart[(size_t)c * (II * NST) + idx] = h;
        h = h * __expf(A * sumdt[c * II + i]) + chunkh[(size_t)c * (II * NST) + idx];
    }
}

// ---------------- scan pass C ----------------
__global__ __launch_bounds__(128) void scan_passC_k(
    const float* __restrict__ dtact, const float* __restrict__ ucl,
    const float* __restrict__ Bn, const float* __restrict__ Cn,
    const float* __restrict__ A_log, const float* __restrict__ hstart,
    const float* __restrict__ Dsk, const float* __restrict__ proj,
    float* __restrict__ mamba)
{
    __shared__ float Bs[CHSZ][NST];
    __shared__ float Cs[CHSZ][NST];
    const int c = blockIdx.y;
    const int i = blockIdx.x * 128 + threadIdx.x;
    for (int idx = threadIdx.x; idx < CHSZ * NST; idx += 128) {
        int t = idx >> 4, n = idx & 15;
        Bs[t][n] = Bn[(size_t)(c * CHSZ + t) * NST + n];
        Cs[t][n] = Cn[(size_t)(c * CHSZ + t) * NST + n];
    }
    __syncthreads();

    float Ai[NST];
#pragma unroll
    for (int n = 0; n < NST; n++) Ai[n] = -__expf(A_log[(size_t)i * NST + n]);
    bool geom = true;
#pragma unroll
    for (int n = 1; n < NST; n++) {
        float ex = Ai[0] * (float)(n + 1);
        if (fabsf(Ai[n] - ex) > 1e-3f * fabsf(ex)) geom = false;
    }

    float h[NST];
#pragma unroll
    for (int n = 0; n < NST; n++) h[n] = hstart[((size_t)c * II + i) * NST + n];
    const float Dv = Dsk[i];

    if (geom) {
        const float a0 = Ai[0];
        for (int t = 0; t < CHSZ; t++) {
            int tg = c * CHSZ + t;
            float dtv = dtact[(size_t)tg * II + i];
            float uv  = ucl[(size_t)tg * II + i];
            float du = dtv * uv;
            float e1 = __expf(dtv * a0);
            float p = e1;
            float y = 0.f;
#pragma unroll
            for (int n = 0; n < NST; n++) {
                h[n] = h[n] * p + du * Bs[t][n];
                y += h[n] * Cs[t][n];
                p *= e1;
            }
            float g = proj[(size_t)tg * 4096 + 2048 + i];
            float sg = g / (1.f + __expf(-g));
            mamba[(size_t)tg * II + i] = (y + uv * Dv) * sg;
        }
    } else {
        for (int t = 0; t < CHSZ; t++) {
            int tg = c * CHSZ + t;
            float dtv = dtact[(size_t)tg * II + i];
            float uv  = ucl[(size_t)tg * II + i];
            float du = dtv * uv;
            float y = 0.f;
#pragma unroll
            for (int n = 0; n < NST; n++) {
                h[n] = h[n] * __expf(dtv * Ai[n]) + du * Bs[t][n];
                y += h[n] * Cs[t][n];
            }
            float g = proj[(size_t)tg * 4096 + 2048 + i];
            float sg = g / (1.f + __expf(-g));
            mamba[(size_t)tg * II + i] = (y + uv * Dv) * sg;
        }
    }
}

// ---------------- RoPE ----------------
__global__ __launch_bounds__(256) void rope_q_k(
    const float* __restrict__ proj, float* __restrict__ qr)
{
    int idx = blockIdx.x * 256 + threadIdx.x;
    int t = idx >> 11, col = idx & 2047, d = col & 127;
    int j = d & 63;
    float ang = (float)t * __expf(-(float)j * 0.14391156831212787f);
    float s, c;
    sincosf(ang, &s, &c);
    float x = proj[(size_t)t * 4096 + col];
    float other = (d < 64) ? proj[(size_t)t * 4096 + col + 64]
                           : proj[(size_t)t * 4096 + col - 64];
    qr[idx] = (d < 64) ? (x * c - other * s) : (x * c + other * s);
}

__global__ __launch_bounds__(256) void rope_k_k(
    const float* __restrict__ klin, float* __restrict__ kr)
{
    int idx = blockIdx.x * 256 + threadIdx.x;
    int t = idx >> 9, col = idx & 511, d = col & 127;
    int j = d & 63;
    float ang = (float)t * __expf(-(float)j * 0.14391156831212787f);
    float s, c;
    sincosf(ang, &s, &c);
    float x = klin[(size_t)t * 512 + col];
    float other = (d < 64) ? klin[(size_t)t * 512 + col + 64]
                           : klin[(size_t)t * 512 + col - 64];
    kr[idx] = (d < 64) ? (x * c - other * s) : (x * c + other * s);
}

// ---------------- flash attention ----------------
__global__ __launch_bounds__(256) void attn_k(
    const float* __restrict__ qr, const float* __restrict__ kr,
    const float* __restrict__ vr, float* __restrict__ attn_out)
{
    extern __shared__ float smem[];
    float* Qs = smem;
    float* Ks = Qs + 8192;
    float* Vs = Ks + 8192;
    float* Ps = Vs + 8192;
    __shared__ float m_s[64], l_s[64], al_s[64];

    const int tid = threadIdx.x;
    const int q0 = blockIdx.x * 64;
    const int h = blockIdx.y;
    const int kvh = h >> 2;
    const float scale = 0.08838834764831845f;

    for (int i = tid * 4; i < 8192; i += 1024) {
        int r = i >> 7, d = i & 127;
        float4 q = *(const float4*)(qr + (size_t)(q0 + r) * 2048 + h * 128 + d);
        q.x *= scale; q.y *= scale; q.z *= scale; q.w *= scale;
        *(float4*)&Qs[i] = q;
    }
    if (tid < 64) { m_s[tid] = -1e30f; l_s[tid] = 0.f; al_s[tid] = 1.f; }

    const int sr = (tid >> 4) << 2;
    const int sc = (tid & 15) << 2;
    const int pc = (tid & 15) << 3;
    float O[4][8];
#pragma unroll
    for (int i = 0; i < 4; i++)
#pragma unroll
        for (int j = 0; j < 8; j++) O[i][j] = 0.f;

    __syncthreads();

    int wstart = q0 - 1024; if (wstart < 128) wstart = 128;

    for (int ti = 0; ti < 20; ti++) {
        int k0;
        if (ti < 2) { k0 = ti << 6; }
        else { k0 = wstart + ((ti - 2) << 6); if (k0 > q0) break; }

        for (int i = tid * 4; i < 8192; i += 1024) {
            int r = i >> 7, d = i & 127;
            size_t off = (size_t)(k0 + r) * 512 + kvh * 128 + d;
            *(float4*)&Ks[i] = *(const float4*)(kr + off);
            *(float4*)&Vs[i] = *(const float4*)(vr + off);
        }
        __syncthreads();

        float s[4][4];
#pragma unroll
        for (int i = 0; i < 4; i++)
#pragma unroll
            for (int j = 0; j < 4; j++) s[i][j] = 0.f;

        for (int kk = 0; kk < 128; kk += 4) {
            float4 a[4], b[4];
#pragma unroll
            for (int i = 0; i < 4; i++) a[i] = *(const float4*)&Qs[(sr + i) * 128 + kk];
#pragma unroll
            for (int j = 0; j < 4; j++) b[j] = *(const float4*)&Ks[(sc + j) * 128 + kk];
#pragma unroll
            for (int i = 0; i < 4; i++)
#pragma unroll
                for (int j = 0; j < 4; j++)
                    s[i][j] += a[i].x * b[j].x + a[i].y * b[j].y + a[i].z * b[j].z + a[i].w * b[j].w;
        }

#pragma unroll
        for (int i = 0; i < 4; i++) {
            int qi = q0 + sr + i;
#pragma unroll
            for (int j = 0; j < 4; j++) {
                int ki = k0 + sc + j;
                bool ok = (ki <= qi) && (((qi - ki) <= 1024) || (ki < 128));
                if (!ok) s[i][j] = -1e30f;
            }
        }

        float rmax[4];
#pragma unroll
        for (int i = 0; i < 4; i++)
            rmax[i] = fmaxf(fmaxf(s[i][0], s[i][1]), fmaxf(s[i][2], s[i][3]));
#pragma unroll
        for (int o = 1; o < 16; o <<= 1)
#pragma unroll
            for (int i = 0; i < 4; i++)
                rmax[i] = fmaxf(rmax[i], __shfl_xor_sync(~0u, rmax[i], o));

        float mo[4], mn[4], rs[4];
#pragma unroll
        for (int i = 0; i < 4; i++) {
            mo[i] = m_s[sr + i];
            mn[i] = fmaxf(mo[i], rmax[i]);
            rs[i] = 0.f;
        }
#pragma unroll
        for (int i = 0; i < 4; i++)
#pragma unroll
            for (int j = 0; j < 4; j++) {
                float p = __expf(s[i][j] - mn[i]);
                Ps[(sr + i) * 64 + sc + j] = p;
                rs[i] += p;
            }
#pragma unroll
        for (int o = 1; o < 16; o <<= 1)
#pragma unroll
            for (int i = 0; i < 4; i++)
                rs[i] += __shfl_xor_sync(~0u, rs[i], o);

        if ((tid & 15) == 0) {
#pragma unroll
            for (int i = 0; i < 4; i++) {
                float al = __expf(mo[i] - mn[i]);
                al_s[sr + i] = al;
                l_s[sr + i] = l_s[sr + i] * al + rs[i];
                m_s[sr + i] = mn[i];
            }
        }
        __syncthreads();

        float al[4];
#pragma unroll
        for (int i = 0; i < 4; i++) al[i] = al_s[sr + i];
#pragma unroll
        for (int i = 0; i < 4; i++)
#pragma unroll
            for (int j = 0; j < 8; j++) O[i][j] *= al[i];

        for (int cix = 0; cix < 64; cix++) {
            float4 v0 = *(const float4*)&Vs[cix * 128 + pc];
            float4 v1 = *(const float4*)&Vs[cix * 128 + pc + 4];
            float p0 = Ps[(sr + 0) * 64 + cix];
            float p1 = Ps[(sr + 1) * 64 + cix];
            float p2 = Ps[(sr + 2) * 64 + cix];
            float p3 = Ps[(sr + 3) * 64 + cix];
            O[0][0] += p0 * v0.x; O[0][1] += p0 * v0.y; O[0][2] += p0 * v0.z; O[0][3] += p0 * v0.w;
            O[0][4] += p0 * v1.x; O[0][5] += p0 * v1.y; O[0][6] += p0 * v1.z; O[0][7] += p0 * v1.w;
            O[1][0] += p1 * v0.x; O[1][1] += p1 * v0.y; O[1][2] += p1 * v0.z; O[1][3] += p1 * v0.w;
            O[1][4] += p1 * v1.x; O[1][5] += p1 * v1.y; O[1][6] += p1 * v1.z; O[1][7] += p1 * v1.w;
            O[2][0] += p2 * v0.x; O[2][1] += p2 * v0.y; O[2][2] += p2 * v0.z; O[2][3] += p2 * v0.w;
            O[2][4] += p2 * v1.x; O[2][5] += p2 * v1.y; O[2][6] += p2 * v1.z; O[2][7] += p2 * v1.w;
            O[3][0] += p3 * v0.x; O[3][1] += p3 * v0.y; O[3][2] += p3 * v0.z; O[3][3] += p3 * v0.w;
            O[3][4] += p3 * v1.x; O[3][5] += p3 * v1.y; O[3][6] += p3 * v1.z; O[3][7] += p3 * v1.w;
        }
        __syncthreads();
    }

#pragma unroll
    for (int i = 0; i < 4; i++) {
        float inv = 1.f / l_s[sr + i];
        float4 o0 = make_float4(O[i][0] * inv, O[i][1] * inv, O[i][2] * inv, O[i][3] * inv);
        float4 o1 = make_float4(O[i][4] * inv, O[i][5] * inv, O[i][6] * inv, O[i][7] * inv);
        float* dst = attn_out + (size_t)(q0 + sr + i) * 2048 + h * 128 + pc;
        *(float4*)dst = o0;
        *(float4*)(dst + 4) = o1;
    }
}

// ---------------- fuse norms ----------------
__global__ __launch_bounds__(256) void fuse_norm_k(
    const float* __restrict__ attn, const float* __restrict__ mamba,
    const float* __restrict__ wa, const float* __restrict__ wm,
    float* __restrict__ fused)
{
    __shared__ float sh[18];
    int t = blockIdx.x, tid = threadIdx.x;
    float av[8], mv[8];
    float sa = 0.f, sm = 0.f;
#pragma unroll
    for (int k = 0; k < 8; k++) {
        int col = tid + k * 256;
        av[k] = attn[(size_t)t * II + col];
        mv[k] = mamba[(size_t)t * II + col];
        sa += av[k] * av[k];
        sm += mv[k] * mv[k];
    }
#pragma unroll
    for (int o = 16; o; o >>= 1) {
        sa += __shfl_xor_sync(~0u, sa, o);
        sm += __shfl_xor_sync(~0u, sm, o);
    }
    int w = tid >> 5;
    if ((tid & 31) == 0) { sh[w] = sa; sh[8 + w] = sm; }
    __syncthreads();
    if (tid == 0) {
        float ta = 0.f, tm = 0.f;
        for (int k = 0; k < 8; k++) { ta += sh[k]; tm += sh[8 + k]; }
        sh[16] = ta; sh[17] = tm;
    }
    __syncthreads();
    float ra = rsqrtf(sh[16] / (float)II + EPSV);
    float rm = rsqrtf(sh[17] / (float)II + EPSV);
#pragma unroll
    for (int k = 0; k < 8; k++) {
        int col = tid + k * 256;
        fused[(size_t)t * II + col] = 0.5f * (av[k] * ra * wa[col] + mv[k] * rm * wm[col]);
    }
}

// ---------------- host ----------------
extern "C" void kernel_launch(void* const* d_in, const int* in_sizes, int n_in,
                              void* d_out, int out_size)
{
    const float* x          = (const float*)d_in[0];
    const float* in_proj_w  = (const float*)d_in[1];
    const float* k_proj_w   = (const float*)d_in[2];
    const float* v_proj_w   = (const float*)d_in[3];
    const float* conv_w     = (const float*)d_in[4];
    const float* conv_b     = (const float*)d_in[5];
    const float* x_proj_w   = (const float*)d_in[6];
    const float* dt_proj_w  = (const float*)d_in[7];
    const float* dt_proj_b  = (const float*)d_in[8];
    const float* A_log      = (const float*)d_in[9];
    const float* D_skip     = (const float*)d_in[10];
    const float* dt_ln_w    = (const float*)d_in[11];
    const float* B_ln_w     = (const float*)d_in[12];
    const float* C_ln_w     = (const float*)d_in[13];
    const float* attn_ln_w  = (const float*)d_in[14];
    const float* mamba_ln_w = (const float*)d_in[15];
    const float* out_proj_w = (const float*)d_in[16];
    float* out = (float*)d_out;

    float *proj, *klin, *vlin, *ucl, *ssm, *dtn, *Bn, *Cn, *dtact;
    float *chunkh, *sumdt, *hstart, *mamba, *qr, *kr, *attn, *fused;
    cudaGetSymbolAddress((void**)&proj,   g_proj);
    cudaGetSymbolAddress((void**)&klin,   g_klin);
    cudaGetSymbolAddress((void**)&vlin,   g_vlin);
    cudaGetSymbolAddress((void**)&ucl,    g_ucl);
    cudaGetSymbolAddress((void**)&ssm,    g_ssm);
    cudaGetSymbolAddress((void**)&dtn,    g_dtn);
    cudaGetSymbolAddress((void**)&Bn,     g_Bn);
    cudaGetSymbolAddress((void**)&Cn,     g_Cn);
    cudaGetSymbolAddress((void**)&dtact,  g_dtact);
    cudaGetSymbolAddress((void**)&chunkh, g_chunkh);
    cudaGetSymbolAddress((void**)&sumdt,  g_sumdt);
    cudaGetSymbolAddress((void**)&hstart, g_hstart);
    cudaGetSymbolAddress((void**)&mamba,  g_mamba);
    cudaGetSymbolAddress((void**)&qr,     g_qr);
    cudaGetSymbolAddress((void**)&kr,     g_kr);
    cudaGetSymbolAddress((void**)&attn,   g_attn);
    cudaGetSymbolAddress((void**)&fused,  g_fused);

    // zero split-K accumulation targets
    cudaMemsetAsync(klin, 0, (size_t)LL * 512 * sizeof(float));
    cudaMemsetAsync(vlin, 0, (size_t)LL * 512 * sizeof(float));
    cudaMemsetAsync(ssm,  0, (size_t)LL * 96 * sizeof(float));

    // projections (tensor-core TF32)
    gemm_tc<<<dim3(32, 16, 1), 256>>>(x, in_proj_w, proj, LL, 4096, DD, nullptr, 0, 1);
    gemm_tc<<<dim3(4, 16, 4), 256>>>(x, k_proj_w, klin, LL, 512, DD, nullptr, 0, 4);
    gemm_tc<<<dim3(4, 16, 4), 256>>>(x, v_proj_w, vlin, LL, 512, DD, nullptr, 0, 4);

    // mamba branch
    conv_silu_k<<<LL * II / 256, 256>>>(proj, conv_w, conv_b, ucl);
    gemm_tc<<<dim3(1, 16, 8), 256>>>(ucl, x_proj_w, ssm, LL, 96, II, nullptr, 0, 8);
    rmsnorm_dtbc_k<<<512, 128>>>(ssm, dt_ln_w, B_ln_w, C_ln_w, dtn, Bn, Cn);
    gemm_tc<<<dim3(16, 16, 1), 256>>>(dtn, dt_proj_w, dtact, LL, II, TSRD, dt_proj_b, 1, 1);
    scan_passA_k<<<dim3(II / 128, NCH), 128>>>(dtact, ucl, Bn, A_log, chunkh, sumdt);
    scan_passB_k<<<(II * NST) / 256, 256>>>(chunkh, sumdt, A_log, hstart);
    scan_passC_k<<<dim3(II / 128, NCH), 128>>>(dtact, ucl, Bn, Cn, A_log, hstart,
                                               D_skip, proj, mamba);

    // attention branch
    rope_q_k<<<LL * II / 256, 256>>>(proj, qr);
    rope_k_k<<<LL * 512 / 256, 256>>>(klin, kr);
    size_t smem = (size_t)(3 * 8192 + 4096) * sizeof(float);
    cudaFuncSetAttribute(attn_k, cudaFuncAttributeMaxDynamicSharedMemorySize, (int)smem);
    attn_k<<<dim3(LL / 64, HQ), 256, smem>>>(qr, kr, vlin, attn);

    // fuse + out projection
    fuse_norm_k<<<LL, 256>>>(attn, mamba, attn_ln_w, mamba_ln_w, fused);
    gemm_tc<<<dim3(8, 16, 1), 256>>>(fused, out_proj_w, out, LL, DD, II, nullptr, 0, 1);
}

// round 9
// speedup vs baseline: 1.2941x; 1.2941x over previous
#include <cuda_runtime.h>
#include <math.h>
#include <stdint.h>

// ---------------- dims ----------------
#define LL   2048
#define DD   1024
#define II   2048
#define NST  16
#define TSRD 64
#define HQ   16
#define NCH  32
#define CHSZ 64
#define EPSV 1e-6f

// ---------------- scratch ----------------
__device__ float g_proj [LL * 2 * II];
__device__ float g_klin [LL * 512];
__device__ float g_vlin [LL * 512];
__device__ float g_ucl  [LL * II];
__device__ float g_ssm  [LL * 96];
__device__ float g_dtn  [LL * TSRD];
__device__ float g_Bn   [LL * NST];
__device__ float g_Cn   [LL * NST];
__device__ float g_dtact[LL * II];
__device__ float g_chunkh[NCH * II * NST];
__device__ float g_sumdt [NCH * II];
__device__ float g_hstart[NCH * II * NST];
__device__ float g_mamba[LL * II];
__device__ float g_qr   [LL * II];
__device__ float g_kr   [LL * 512];
__device__ float g_attn [LL * II];
__device__ float g_fused[LL * II];

// ---------------- cp.async helpers ----------------
__device__ __forceinline__ void cp_async16(void* smem_dst, const void* gmem_src, int src_bytes) {
    uint32_t saddr = (uint32_t)__cvta_generic_to_shared(smem_dst);
    asm volatile("cp.async.cg.shared.global [%0], [%1], 16, %2;"
                 :: "r"(saddr), "l"(gmem_src), "r"(src_bytes));
}
__device__ __forceinline__ void cp_commit() {
    asm volatile("cp.async.commit_group;");
}
__device__ __forceinline__ void cp_wait0() {
    asm volatile("cp.async.wait_group 0;");
}

// ---------------- SGEMM: 128x128x8, 8x8/thread, cp.async double-buffered B + reg-prefetch A ----------------
// nsplit>1: blockIdx.z = K-split; partials atomicAdd'ed into pre-zeroed C.
__global__ __launch_bounds__(256) void gemm_k(
    const float* __restrict__ A, const float* __restrict__ B, float* __restrict__ C,
    int M, int N, int K, const float* __restrict__ bias, int act, int nsplit)
{
    __shared__ float As[2][8][128];
    __shared__ float Bs[2][8][128];
    const int tid = threadIdx.x;
    const int m0 = blockIdx.y * 128;
    const int n0 = blockIdx.x * 128;
    const int klen = K / nsplit;
    const int ks = blockIdx.z * klen;
    const int nk = klen / 8;
    const int tr = (tid >> 4) * 8;
    const int tc = (tid & 15) * 8;

    float acc[8][8];
#pragma unroll
    for (int i = 0; i < 8; i++)
#pragma unroll
        for (int j = 0; j < 8; j++) acc[i][j] = 0.f;

    const int la_m = tid >> 1;           // 0..127
    const int la_k = (tid & 1) * 4;      // 0 or 4
    const int lb_k = tid >> 5;           // 0..7
    const int lb_n = (tid & 31) * 4;     // 0..124

    const float* Ap = A + (size_t)(m0 + la_m) * K + ks + la_k;
    const int gn = n0 + lb_n;
    const float* Bp = B + (size_t)(ks + lb_k) * N + gn;
    int bbytes = (N - gn) * 4;
    if (bbytes < 0) bbytes = 0;
    if (bbytes > 16) bbytes = 16;

    // preload tile 0
    {
        float4 av = *(const float4*)(Ap);
        As[0][la_k + 0][la_m] = av.x;
        As[0][la_k + 1][la_m] = av.y;
        As[0][la_k + 2][la_m] = av.z;
        As[0][la_k + 3][la_m] = av.w;
        if (bbytes < 16) {  // zero pad lanes that zero-fill (keeps stale smem out)
            float* d = &Bs[0][lb_k][lb_n];
            d[0] = d[1] = d[2] = d[3] = 0.f;
        }
        cp_async16(&Bs[0][lb_k][lb_n], Bp, bbytes);
        cp_commit();
        cp_wait0();
    }
    __syncthreads();

    for (int kt = 0; kt < nk; kt++) {
        const int cur = kt & 1, nxt = cur ^ 1;
        const bool have = (kt + 1 < nk);
        float4 avn;
        if (have) {
            avn = *(const float4*)(Ap + (kt + 1) * 8);
            if (bbytes < 16) {
                float* d = &Bs[nxt][lb_k][lb_n];
                d[0] = d[1] = d[2] = d[3] = 0.f;
            }
            cp_async16(&Bs[nxt][lb_k][lb_n], Bp + (size_t)(kt + 1) * 8 * N, bbytes);
            cp_commit();
        }

#pragma unroll
        for (int kk = 0; kk < 8; kk++) {
            float a[8], b[8];
            *(float4*)&a[0] = *(const float4*)&As[cur][kk][tr];
            *(float4*)&a[4] = *(const float4*)&As[cur][kk][tr + 4];
            *(float4*)&b[0] = *(const float4*)&Bs[cur][kk][tc];
            *(float4*)&b[4] = *(const float4*)&Bs[cur][kk][tc + 4];
#pragma unroll
            for (int i = 0; i < 8; i++)
#pragma unroll
                for (int j = 0; j < 8; j++) acc[i][j] += a[i] * b[j];
        }

        if (have) {
            As[nxt][la_k + 0][la_m] = avn.x;
            As[nxt][la_k + 1][la_m] = avn.y;
            As[nxt][la_k + 2][la_m] = avn.z;
            As[nxt][la_k + 3][la_m] = avn.w;
            cp_wait0();
        }
        __syncthreads();
    }

#pragma unroll
    for (int i = 0; i < 8; i++) {
        int row = m0 + tr + i;
#pragma unroll
        for (int j = 0; j < 8; j++) {
            int col = n0 + tc + j;
            if (col < N) {
                float v = acc[i][j];
                if (nsplit > 1) {
                    atomicAdd(&C[(size_t)row * N + col], v);
                } else {
                    if (act == 1) {
                        float xx = v + bias[col];
                        v = fmaxf(xx, 0.f) + log1pf(__expf(-fabsf(xx)));
                    }
                    C[(size_t)row * N + col] = v;
                }
            }
        }
    }
}

// ---------------- conv K=4 + SiLU ----------------
__global__ __launch_bounds__(256) void conv_silu_k(
    const float* __restrict__ proj, const float* __restrict__ cw,
    const float* __restrict__ cb, float* __restrict__ ucl)
{
    int idx = blockIdx.x * 256 + threadIdx.x;
    int t = idx >> 11, i = idx & 2047;
    float4 w = *(const float4*)(cw + i * 4);
    float acc = cb[i];
    if (t >= 3) acc += proj[(size_t)(t - 3) * 4096 + i] * w.x;
    if (t >= 2) acc += proj[(size_t)(t - 2) * 4096 + i] * w.y;
    if (t >= 1) acc += proj[(size_t)(t - 1) * 4096 + i] * w.z;
    acc += proj[(size_t)t * 4096 + i] * w.w;
    ucl[idx] = acc / (1.f + __expf(-acc));
}

// ---------------- rmsnorm dt/B/C ----------------
__global__ __launch_bounds__(128) void rmsnorm_dtbc_k(
    const float* __restrict__ ssm, const float* __restrict__ wdt,
    const float* __restrict__ wB, const float* __restrict__ wC,
    float* __restrict__ dtn, float* __restrict__ Bn, float* __restrict__ Cn)
{
    int warp = (blockIdx.x * blockDim.x + threadIdx.x) >> 5;
    int lane = threadIdx.x & 31;
    if (warp >= LL) return;
    const float* row = ssm + (size_t)warp * 96;

    float v0 = row[lane], v1 = row[lane + 32];
    float ss = v0 * v0 + v1 * v1;
#pragma unroll
    for (int o = 16; o; o >>= 1) ss += __shfl_xor_sync(~0u, ss, o);
    float r = rsqrtf(ss / 64.f + EPSV);
    dtn[warp * 64 + lane]      = v0 * r * wdt[lane];
    dtn[warp * 64 + lane + 32] = v1 * r * wdt[lane + 32];

    float b = (lane < 16) ? row[64 + lane] : 0.f;
    float sb = b * b;
#pragma unroll
    for (int o = 16; o; o >>= 1) sb += __shfl_xor_sync(~0u, sb, o);
    float rb = rsqrtf(sb / 16.f + EPSV);
    if (lane < 16) Bn[warp * 16 + lane] = b * rb * wB[lane];

    float c = (lane < 16) ? row[80 + lane] : 0.f;
    float sc = c * c;
#pragma unroll
    for (int o = 16; o; o >>= 1) sc += __shfl_xor_sync(~0u, sc, o);
    float rc = rsqrtf(sc / 16.f + EPSV);
    if (lane < 16) Cn[warp * 16 + lane] = c * rc * wC[lane];
}

// ---------------- scan pass A ----------------
__global__ __launch_bounds__(128) void scan_passA_k(
    const float* __restrict__ dtact, const float* __restrict__ ucl,
    const float* __restrict__ Bn, const float* __restrict__ A_log,
    float* __restrict__ chunkh, float* __restrict__ sumdt)
{
    __shared__ float Bs[CHSZ][NST];
    const int c = blockIdx.y;
    const int i = blockIdx.x * 128 + threadIdx.x;
    for (int idx = threadIdx.x; idx < CHSZ * NST; idx += 128)
        Bs[idx >> 4][idx & 15] = Bn[(size_t)(c * CHSZ + (idx >> 4)) * NST + (idx & 15)];
    __syncthreads();

    float Ai[NST];
#pragma unroll
    for (int n = 0; n < NST; n++) Ai[n] = -__expf(A_log[(size_t)i * NST + n]);
    bool geom = true;
#pragma unroll
    for (int n = 1; n < NST; n++) {
        float ex = Ai[0] * (float)(n + 1);
        if (fabsf(Ai[n] - ex) > 1e-3f * fabsf(ex)) geom = false;
    }

    float h[NST];
#pragma unroll
    for (int n = 0; n < NST; n++) h[n] = 0.f;
    float sdt = 0.f;

    if (geom) {
        const float a0 = Ai[0];
        for (int t = 0; t < CHSZ; t++) {
            int tg = c * CHSZ + t;
            float dtv = dtact[(size_t)tg * II + i];
            float uv  = ucl[(size_t)tg * II + i];
            sdt += dtv;
            float du = dtv * uv;
            float e1 = __expf(dtv * a0);
            float p = e1;
#pragma unroll
            for (int n = 0; n < NST; n++) {
                h[n] = h[n] * p + du * Bs[t][n];
                p *= e1;
            }
        }
    } else {
        for (int t = 0; t < CHSZ; t++) {
            int tg = c * CHSZ + t;
            float dtv = dtact[(size_t)tg * II + i];
            float uv  = ucl[(size_t)tg * II + i];
            sdt += dtv;
            float du = dtv * uv;
#pragma unroll
            for (int n = 0; n < NST; n++)
                h[n] = h[n] * __expf(dtv * Ai[n]) + du * Bs[t][n];
        }
    }
#pragma unroll
    for (int n = 0; n < NST; n++)
        chunkh[((size_t)c * II + i) * NST + n] = h[n];
    sumdt[c * II + i] = sdt;
}

// ---------------- scan pass B ----------------
__global__ __launch_bounds__(256) void scan_passB_k(
    const float* __restrict__ chunkh, const float* __restrict__ sumdt,
    const float* __restrict__ A_log, float* __restrict__ hstart)
{
    int idx = blockIdx.x * 256 + threadIdx.x;
    int i = idx >> 4;
    float A = -__expf(A_log[idx]);
    float h = 0.f;
    for (int c = 0; c < NCH; c++) {
        hstart[(size_t)c * (II * NST) + idx] = h;
        h = h * __expf(A * sumdt[c * II + i]) + chunkh[(size_t)c * (II * NST) + idx];
    }
}

// ---------------- scan pass C ----------------
__global__ __launch_bounds__(128) void scan_passC_k(
    const float* __restrict__ dtact, const float* __restrict__ ucl,
    const float* __restrict__ Bn, const float* __restrict__ Cn,
    const float* __restrict__ A_log, const float* __restrict__ hstart,
    const float* __restrict__ Dsk, const float* __restrict__ proj,
    float* __restrict__ mamba)
{
    __shared__ float Bs[CHSZ][NST];
    __shared__ float Cs[CHSZ][NST];
    const int c = blockIdx.y;
    const int i = blockIdx.x * 128 + threadIdx.x;
    for (int idx = threadIdx.x; idx < CHSZ * NST; idx += 128) {
        int t = idx >> 4, n = idx & 15;
        Bs[t][n] = Bn[(size_t)(c * CHSZ + t) * NST + n];
        Cs[t][n] = Cn[(size_t)(c * CHSZ + t) * NST + n];
    }
    __syncthreads();

    float Ai[NST];
#pragma unroll
    for (int n = 0; n < NST; n++) Ai[n] = -__expf(A_log[(size_t)i * NST + n]);
    bool geom = true;
#pragma unroll
    for (int n = 1; n < NST; n++) {
        float ex = Ai[0] * (float)(n + 1);
        if (fabsf(Ai[n] - ex) > 1e-3f * fabsf(ex)) geom = false;
    }

    float h[NST];
#pragma unroll
    for (int n = 0; n < NST; n++) h[n] = hstart[((size_t)c * II + i) * NST + n];
    const float Dv = Dsk[i];

    if (geom) {
        const float a0 = Ai[0];
        for (int t = 0; t < CHSZ; t++) {
            int tg = c * CHSZ + t;
            float dtv = dtact[(size_t)tg * II + i];
            float uv  = ucl[(size_t)tg * II + i];
            float du = dtv * uv;
            float e1 = __expf(dtv * a0);
            float p = e1;
            float y = 0.f;
#pragma unroll
            for (int n = 0; n < NST; n++) {
                h[n] = h[n] * p + du * Bs[t][n];
                y += h[n] * Cs[t][n];
                p *= e1;
            }
            float g = proj[(size_t)tg * 4096 + 2048 + i];
            float sg = g / (1.f + __expf(-g));
            mamba[(size_t)tg * II + i] = (y + uv * Dv) * sg;
        }
    } else {
        for (int t = 0; t < CHSZ; t++) {
            int tg = c * CHSZ + t;
            float dtv = dtact[(size_t)tg * II + i];
            float uv  = ucl[(size_t)tg * II + i];
            float du = dtv * uv;
            float y = 0.f;
#pragma unroll
            for (int n = 0; n < NST; n++) {
                h[n] = h[n] * __expf(dtv * Ai[n]) + du * Bs[t][n];
                y += h[n] * Cs[t][n];
            }
            float g = proj[(size_t)tg * 4096 + 2048 + i];
            float sg = g / (1.f + __expf(-g));
            mamba[(size_t)tg * II + i] = (y + uv * Dv) * sg;
        }
    }
}

// ---------------- RoPE ----------------
__global__ __launch_bounds__(256) void rope_q_k(
    const float* __restrict__ proj, float* __restrict__ qr)
{
    int idx = blockIdx.x * 256 + threadIdx.x;
    int t = idx >> 11, col = idx & 2047, d = col & 127;
    int j = d & 63;
    float ang = (float)t * __expf(-(float)j * 0.14391156831212787f);
    float s, c;
    sincosf(ang, &s, &c);
    float x = proj[(size_t)t * 4096 + col];
    float other = (d < 64) ? proj[(size_t)t * 4096 + col + 64]
                           : proj[(size_t)t * 4096 + col - 64];
    qr[idx] = (d < 64) ? (x * c - other * s) : (x * c + other * s);
}

__global__ __launch_bounds__(256) void rope_k_k(
    const float* __restrict__ klin, float* __restrict__ kr)
{
    int idx = blockIdx.x * 256 + threadIdx.x;
    int t = idx >> 9, col = idx & 511, d = col & 127;
    int j = d & 63;
    float ang = (float)t * __expf(-(float)j * 0.14391156831212787f);
    float s, c;
    sincosf(ang, &s, &c);
    float x = klin[(size_t)t * 512 + col];
    float other = (d < 64) ? klin[(size_t)t * 512 + col + 64]
                           : klin[(size_t)t * 512 + col - 64];
    kr[idx] = (d < 64) ? (x * c - other * s) : (x * c + other * s);
}

// ---------------- flash attention ----------------
__global__ __launch_bounds__(256) void attn_k(
    const float* __restrict__ qr, const float* __restrict__ kr,
    const float* __restrict__ vr, float* __restrict__ attn_out)
{
    extern __shared__ float smem[];
    float* Qs = smem;
    float* Ks = Qs + 8192;
    float* Vs = Ks + 8192;
    float* Ps = Vs + 8192;
    __shared__ float m_s[64], l_s[64], al_s[64];

    const int tid = threadIdx.x;
    const int q0 = blockIdx.x * 64;
    const int h = blockIdx.y;
    const int kvh = h >> 2;
    const float scale = 0.08838834764831845f;

    for (int i = tid * 4; i < 8192; i += 1024) {
        int r = i >> 7, d = i & 127;
        float4 q = *(const float4*)(qr + (size_t)(q0 + r) * 2048 + h * 128 + d);
        q.x *= scale; q.y *= scale; q.z *= scale; q.w *= scale;
        *(float4*)&Qs[i] = q;
    }
    if (tid < 64) { m_s[tid] = -1e30f; l_s[tid] = 0.f; al_s[tid] = 1.f; }

    const int sr = (tid >> 4) << 2;
    const int sc = (tid & 15) << 2;
    const int pc = (tid & 15) << 3;
    float O[4][8];
#pragma unroll
    for (int i = 0; i < 4; i++)
#pragma unroll
        for (int j = 0; j < 8; j++) O[i][j] = 0.f;

    __syncthreads();

    int wstart = q0 - 1024; if (wstart < 128) wstart = 128;

    for (int ti = 0; ti < 20; ti++) {
        int k0;
        if (ti < 2) { k0 = ti << 6; }
        else { k0 = wstart + ((ti - 2) << 6); if (k0 > q0) break; }

        for (int i = tid * 4; i < 8192; i += 1024) {
            int r = i >> 7, d = i & 127;
            size_t off = (size_t)(k0 + r) * 512 + kvh * 128 + d;
            *(float4*)&Ks[i] = *(const float4*)(kr + off);
            *(float4*)&Vs[i] = *(const float4*)(vr + off);
        }
        __syncthreads();

        float s[4][4];
#pragma unroll
        for (int i = 0; i < 4; i++)
#pragma unroll
            for (int j = 0; j < 4; j++) s[i][j] = 0.f;

        for (int kk = 0; kk < 128; kk += 4) {
            float4 a[4], b[4];
#pragma unroll
            for (int i = 0; i < 4; i++) a[i] = *(const float4*)&Qs[(sr + i) * 128 + kk];
#pragma unroll
            for (int j = 0; j < 4; j++) b[j] = *(const float4*)&Ks[(sc + j) * 128 + kk];
#pragma unroll
            for (int i = 0; i < 4; i++)
#pragma unroll
                for (int j = 0; j < 4; j++)
                    s[i][j] += a[i].x * b[j].x + a[i].y * b[j].y + a[i].z * b[j].z + a[i].w * b[j].w;
        }

#pragma unroll
        for (int i = 0; i < 4; i++) {
            int qi = q0 + sr + i;
#pragma unroll
            for (int j = 0; j < 4; j++) {
                int ki = k0 + sc + j;
                bool ok = (ki <= qi) && (((qi - ki) <= 1024) || (ki < 128));
                if (!ok) s[i][j] = -1e30f;
            }
        }

        float rmax[4];
#pragma unroll
        for (int i = 0; i < 4; i++)
            rmax[i] = fmaxf(fmaxf(s[i][0], s[i][1]), fmaxf(s[i][2], s[i][3]));
#pragma unroll
        for (int o = 1; o < 16; o <<= 1)
#pragma unroll
            for (int i = 0; i < 4; i++)
                rmax[i] = fmaxf(rmax[i], __shfl_xor_sync(~0u, rmax[i], o));

        float mo[4], mn[4], rs[4];
#pragma unroll
        for (int i = 0; i < 4; i++) {
            mo[i] = m_s[sr + i];
            mn[i] = fmaxf(mo[i], rmax[i]);
            rs[i] = 0.f;
        }
#pragma unroll
        for (int i = 0; i < 4; i++)
#pragma unroll
            for (int j = 0; j < 4; j++) {
                float p = __expf(s[i][j] - mn[i]);
                Ps[(sr + i) * 64 + sc + j] = p;
                rs[i] += p;
            }
#pragma unroll
        for (int o = 1; o < 16; o <<= 1)
#pragma unroll
            for (int i = 0; i < 4; i++)
                rs[i] += __shfl_xor_sync(~0u, rs[i], o);

        if ((tid & 15) == 0) {
#pragma unroll
            for (int i = 0; i < 4; i++) {
                float al = __expf(mo[i] - mn[i]);
                al_s[sr + i] = al;
                l_s[sr + i] = l_s[sr + i] * al + rs[i];
                m_s[sr + i] = mn[i];
            }
        }
        __syncthreads();

        float al[4];
#pragma unroll
        for (int i = 0; i < 4; i++) al[i] = al_s[sr + i];
#pragma unroll
        for (int i = 0; i < 4; i++)
#pragma unroll
            for (int j = 0; j < 8; j++) O[i][j] *= al[i];

        for (int cix = 0; cix < 64; cix++) {
            float4 v0 = *(const float4*)&Vs[cix * 128 + pc];
            float4 v1 = *(const float4*)&Vs[cix * 128 + pc + 4];
            float p0 = Ps[(sr + 0) * 64 + cix];
            float p1 = Ps[(sr + 1) * 64 + cix];
            float p2 = Ps[(sr + 2) * 64 + cix];
            float p3 = Ps[(sr + 3) * 64 + cix];
            O[0][0] += p0 * v0.x; O[0][1] += p0 * v0.y; O[0][2] += p0 * v0.z; O[0][3] += p0 * v0.w;
            O[0][4] += p0 * v1.x; O[0][5] += p0 * v1.y; O[0][6] += p0 * v1.z; O[0][7] += p0 * v1.w;
            O[1][0] += p1 * v0.x; O[1][1] += p1 * v0.y; O[1][2] += p1 * v0.z; O[1][3] += p1 * v0.w;
            O[1][4] += p1 * v1.x; O[1][5] += p1 * v1.y; O[1][6] += p1 * v1.z; O[1][7] += p1 * v1.w;
            O[2][0] += p2 * v0.x; O[2][1] += p2 * v0.y; O[2][2] += p2 * v0.z; O[2][3] += p2 * v0.w;
            O[2][4] += p2 * v1.x; O[2][5] += p2 * v1.y; O[2][6] += p2 * v1.z; O[2][7] += p2 * v1.w;
            O[3][0] += p3 * v0.x; O[3][1] += p3 * v0.y; O[3][2] += p3 * v0.z; O[3][3] += p3 * v0.w;
            O[3][4] += p3 * v1.x; O[3][5] += p3 * v1.y; O[3][6] += p3 * v1.z; O[3][7] += p3 * v1.w;
        }
        __syncthreads();
    }

#pragma unroll
    for (int i = 0; i < 4; i++) {
        float inv = 1.f / l_s[sr + i];
        float4 o0 = make_float4(O[i][0] * inv, O[i][1] * inv, O[i][2] * inv, O[i][3] * inv);
        float4 o1 = make_float4(O[i][4] * inv, O[i][5] * inv, O[i][6] * inv, O[i][7] * inv);
        float* dst = attn_out + (size_t)(q0 + sr + i) * 2048 + h * 128 + pc;
        *(float4*)dst = o0;
        *(float4*)(dst + 4) = o1;
    }
}

// ---------------- fuse norms ----------------
__global__ __launch_bounds__(256) void fuse_norm_k(
    const float* __restrict__ attn, const float* __restrict__ mamba,
    const float* __restrict__ wa, const float* __restrict__ wm,
    float* __restrict__ fused)
{
    __shared__ float sh[18];
    int t = blockIdx.x, tid = threadIdx.x;
    float av[8], mv[8];
    float sa = 0.f, sm = 0.f;
#pragma unroll
    for (int k = 0; k < 8; k++) {
        int col = tid + k * 256;
        av[k] = attn[(size_t)t * II + col];
        mv[k] = mamba[(size_t)t * II + col];
        sa += av[k] * av[k];
        sm += mv[k] * mv[k];
    }
#pragma unroll
    for (int o = 16; o; o >>= 1) {
        sa += __shfl_xor_sync(~0u, sa, o);
        sm += __shfl_xor_sync(~0u, sm, o);
    }
    int w = tid >> 5;
    if ((tid & 31) == 0) { sh[w] = sa; sh[8 + w] = sm; }
    __syncthreads();
    if (tid == 0) {
        float ta = 0.f, tm = 0.f;
        for (int k = 0; k < 8; k++) { ta += sh[k]; tm += sh[8 + k]; }
        sh[16] = ta; sh[17] = tm;
    }
    __syncthreads();
    float ra = rsqrtf(sh[16] / (float)II + EPSV);
    float rm = rsqrtf(sh[17] / (float)II + EPSV);
#pragma unroll
    for (int k = 0; k < 8; k++) {
        int col = tid + k * 256;
        fused[(size_t)t * II + col] = 0.5f * (av[k] * ra * wa[col] + mv[k] * rm * wm[col]);
    }
}

// ---------------- host ----------------
extern "C" void kernel_launch(void* const* d_in, const int* in_sizes, int n_in,
                              void* d_out, int out_size)
{
    const float* x          = (const float*)d_in[0];
    const float* in_proj_w  = (const float*)d_in[1];
    const float* k_proj_w   = (const float*)d_in[2];
    const float* v_proj_w   = (const float*)d_in[3];
    const float* conv_w     = (const float*)d_in[4];
    const float* conv_b     = (const float*)d_in[5];
    const float* x_proj_w   = (const float*)d_in[6];
    const float* dt_proj_w  = (const float*)d_in[7];
    const float* dt_proj_b  = (const float*)d_in[8];
    const float* A_log      = (const float*)d_in[9];
    const float* D_skip     = (const float*)d_in[10];
    const float* dt_ln_w    = (const float*)d_in[11];
    const float* B_ln_w     = (const float*)d_in[12];
    const float* C_ln_w     = (const float*)d_in[13];
    const float* attn_ln_w  = (const float*)d_in[14];
    const float* mamba_ln_w = (const float*)d_in[15];
    const float* out_proj_w = (const float*)d_in[16];
    float* out = (float*)d_out;

    float *proj, *klin, *vlin, *ucl, *ssm, *dtn, *Bn, *Cn, *dtact;
    float *chunkh, *sumdt, *hstart, *mamba, *qr, *kr, *attn, *fused;
    cudaGetSymbolAddress((void**)&proj,   g_proj);
    cudaGetSymbolAddress((void**)&klin,   g_klin);
    cudaGetSymbolAddress((void**)&vlin,   g_vlin);
    cudaGetSymbolAddress((void**)&ucl,    g_ucl);
    cudaGetSymbolAddress((void**)&ssm,    g_ssm);
    cudaGetSymbolAddress((void**)&dtn,    g_dtn);
    cudaGetSymbolAddress((void**)&Bn,     g_Bn);
    cudaGetSymbolAddress((void**)&Cn,     g_Cn);
    cudaGetSymbolAddress((void**)&dtact,  g_dtact);
    cudaGetSymbolAddress((void**)&chunkh, g_chunkh);
    cudaGetSymbolAddress((void**)&sumdt,  g_sumdt);
    cudaGetSymbolAddress((void**)&hstart, g_hstart);
    cudaGetSymbolAddress((void**)&mamba,  g_mamba);
    cudaGetSymbolAddress((void**)&qr,     g_qr);
    cudaGetSymbolAddress((void**)&kr,     g_kr);
    cudaGetSymbolAddress((void**)&attn,   g_attn);
    cudaGetSymbolAddress((void**)&fused,  g_fused);

    // zero split-K accumulation targets
    cudaMemsetAsync(klin, 0, (size_t)LL * 512 * sizeof(float));
    cudaMemsetAsync(vlin, 0, (size_t)LL * 512 * sizeof(float));
    cudaMemsetAsync(ssm,  0, (size_t)LL * 96 * sizeof(float));

    // projections
    gemm_k<<<dim3(32, 16, 1), 256>>>(x, in_proj_w, proj, LL, 4096, DD, nullptr, 0, 1);
    gemm_k<<<dim3(4, 16, 4), 256>>>(x, k_proj_w, klin, LL, 512, DD, nullptr, 0, 4);
    gemm_k<<<dim3(4, 16, 4), 256>>>(x, v_proj_w, vlin, LL, 512, DD, nullptr, 0, 4);

    // mamba branch
    conv_silu_k<<<LL * II / 256, 256>>>(proj, conv_w, conv_b, ucl);
    gemm_k<<<dim3(1, 16, 8), 256>>>(ucl, x_proj_w, ssm, LL, 96, II, nullptr, 0, 8);
    rmsnorm_dtbc_k<<<512, 128>>>(ssm, dt_ln_w, B_ln_w, C_ln_w, dtn, Bn, Cn);
    gemm_k<<<dim3(16, 16, 1), 256>>>(dtn, dt_proj_w, dtact, LL, II, TSRD, dt_proj_b, 1, 1);
    scan_passA_k<<<dim3(II / 128, NCH), 128>>>(dtact, ucl, Bn, A_log, chunkh, sumdt);
    scan_passB_k<<<(II * NST) / 256, 256>>>(chunkh, sumdt, A_log, hstart);
    scan_passC_k<<<dim3(II / 128, NCH), 128>>>(dtact, ucl, Bn, Cn, A_log, hstart,
                                               D_skip, proj, mamba);

    // attention branch
    rope_q_k<<<LL * II / 256, 256>>>(proj, qr);
    rope_k_k<<<LL * 512 / 256, 256>>>(klin, kr);
    size_t smem = (size_t)(3 * 8192 + 4096) * sizeof(float);
    cudaFuncSetAttribute(attn_k, cudaFuncAttributeMaxDynamicSharedMemorySize, (int)smem);
    attn_k<<<dim3(LL / 64, HQ), 256, smem>>>(qr, kr, vlin, attn);

    // fuse + out projection
    fuse_norm_k<<<LL, 256>>>(attn, mamba, attn_ln_w, mamba_ln_w, fused);
    gemm_k<<<dim3(8, 16, 1), 256>>>(fused, out_proj_w, out, LL, DD, II, nullptr, 0, 1);
}

// round 10
// speedup vs baseline: 1.3137x; 1.0152x over previous
#include <cuda_runtime.h>
#include <math.h>
#include <stdint.h>

// ---------------- dims ----------------
#define LL   2048
#define DD   1024
#define II   2048
#define NST  16
#define TSRD 64
#define HQ   16
#define NCH  32
#define CHSZ 64
#define EPSV 1e-6f

typedef unsigned long long u64;

// ---------------- packed f32x2 helpers (Blackwell FFMA2) ----------------
__device__ __forceinline__ u64 pack2(float lo, float hi) {
    u64 r; asm("mov.b64 %0, {%1, %2};" : "=l"(r) : "f"(lo), "f"(hi)); return r;
}
__device__ __forceinline__ float2 unpack2(u64 v) {
    float2 r; asm("mov.b64 {%0, %1}, %2;" : "=f"(r.x), "=f"(r.y) : "l"(v)); return r;
}
__device__ __forceinline__ void fma2(u64& d, u64 a, u64 b) {
    asm("fma.rn.f32x2 %0, %1, %2, %0;" : "+l"(d) : "l"(a), "l"(b));
}
__device__ __forceinline__ void mul2(u64& d, u64 a) {
    asm("mul.rn.f32x2 %0, %0, %1;" : "+l"(d) : "l"(a));
}

// ---------------- scratch ----------------
__device__ float g_proj [LL * 2 * II];
__device__ float g_klin [LL * 512];
__device__ float g_vlin [LL * 512];
__device__ float g_ucl  [LL * II];
__device__ float g_ssm  [LL * 96];
__device__ float g_dtn  [LL * TSRD];
__device__ float g_Bn   [LL * NST];
__device__ float g_Cn   [LL * NST];
__device__ float g_dtact[LL * II];
__device__ float g_chunkh[NCH * II * NST];
__device__ float g_sumdt [NCH * II];
__device__ float g_hstart[NCH * II * NST];
__device__ float g_mamba[LL * II];
__device__ float g_qr   [LL * II];
__device__ float g_kr   [LL * 512];
__device__ float g_attn [LL * II];
__device__ float g_fused[LL * II];

// ---------------- cp.async helpers ----------------
__device__ __forceinline__ void cp_async16(void* smem_dst, const void* gmem_src, int src_bytes) {
    uint32_t saddr = (uint32_t)__cvta_generic_to_shared(smem_dst);
    asm volatile("cp.async.cg.shared.global [%0], [%1], 16, %2;"
                 :: "r"(saddr), "l"(gmem_src), "r"(src_bytes));
}
__device__ __forceinline__ void cp_commit() {
    asm volatile("cp.async.commit_group;");
}
__device__ __forceinline__ void cp_wait0() {
    asm volatile("cp.async.wait_group 0;");
}

// ---------------- SGEMM: 128x128x8, 8x8/thread, cp.async DB + FFMA2 inner ----------------
__global__ __launch_bounds__(256) void gemm_k(
    const float* __restrict__ A, const float* __restrict__ B, float* __restrict__ C,
    int M, int N, int K, const float* __restrict__ bias, int act, int nsplit)
{
    __shared__ float As[2][8][128];
    __shared__ float Bs[2][8][128];
    const int tid = threadIdx.x;
    const int m0 = blockIdx.y * 128;
    const int n0 = blockIdx.x * 128;
    const int klen = K / nsplit;
    const int ks = blockIdx.z * klen;
    const int nk = klen / 8;
    const int tr = (tid >> 4) * 8;
    const int tc = (tid & 15) * 8;

    u64 acc2[8][4];
#pragma unroll
    for (int i = 0; i < 8; i++)
#pragma unroll
        for (int jp = 0; jp < 4; jp++) acc2[i][jp] = 0ull;

    const int la_m = tid >> 1;
    const int la_k = (tid & 1) * 4;
    const int lb_k = tid >> 5;
    const int lb_n = (tid & 31) * 4;

    const float* Ap = A + (size_t)(m0 + la_m) * K + ks + la_k;
    const int gn = n0 + lb_n;
    const float* Bp = B + (size_t)(ks + lb_k) * N + gn;
    int bbytes = (N - gn) * 4;
    if (bbytes < 0) bbytes = 0;
    if (bbytes > 16) bbytes = 16;

    // preload tile 0
    {
        float4 av = *(const float4*)(Ap);
        As[0][la_k + 0][la_m] = av.x;
        As[0][la_k + 1][la_m] = av.y;
        As[0][la_k + 2][la_m] = av.z;
        As[0][la_k + 3][la_m] = av.w;
        if (bbytes < 16) {
            float* d = &Bs[0][lb_k][lb_n];
            d[0] = d[1] = d[2] = d[3] = 0.f;
        }
        cp_async16(&Bs[0][lb_k][lb_n], Bp, bbytes);
        cp_commit();
        cp_wait0();
    }
    __syncthreads();

    for (int kt = 0; kt < nk; kt++) {
        const int cur = kt & 1, nxt = cur ^ 1;
        const bool have = (kt + 1 < nk);
        float4 avn;
        if (have) {
            avn = *(const float4*)(Ap + (kt + 1) * 8);
            if (bbytes < 16) {
                float* d = &Bs[nxt][lb_k][lb_n];
                d[0] = d[1] = d[2] = d[3] = 0.f;
            }
            cp_async16(&Bs[nxt][lb_k][lb_n], Bp + (size_t)(kt + 1) * 8 * N, bbytes);
            cp_commit();
        }

#pragma unroll
        for (int kk = 0; kk < 8; kk++) {
            float a[8];
            *(float4*)&a[0] = *(const float4*)&As[cur][kk][tr];
            *(float4*)&a[4] = *(const float4*)&As[cur][kk][tr + 4];
            ulonglong2 bq0 = *(const ulonglong2*)&Bs[cur][kk][tc];
            ulonglong2 bq1 = *(const ulonglong2*)&Bs[cur][kk][tc + 4];
            u64 b2[4] = { bq0.x, bq0.y, bq1.x, bq1.y };
#pragma unroll
            for (int i = 0; i < 8; i++) {
                u64 a2 = pack2(a[i], a[i]);
#pragma unroll
                for (int jp = 0; jp < 4; jp++)
                    fma2(acc2[i][jp], a2, b2[jp]);
            }
        }

        if (have) {
            As[nxt][la_k + 0][la_m] = avn.x;
            As[nxt][la_k + 1][la_m] = avn.y;
            As[nxt][la_k + 2][la_m] = avn.z;
            As[nxt][la_k + 3][la_m] = avn.w;
            cp_wait0();
        }
        __syncthreads();
    }

#pragma unroll
    for (int i = 0; i < 8; i++) {
        int row = m0 + tr + i;
#pragma unroll
        for (int jp = 0; jp < 4; jp++) {
            float2 v2 = unpack2(acc2[i][jp]);
            float vv[2] = { v2.x, v2.y };
#pragma unroll
            for (int e = 0; e < 2; e++) {
                int col = n0 + tc + jp * 2 + e;
                if (col < N) {
                    float v = vv[e];
                    if (nsplit > 1) {
                        atomicAdd(&C[(size_t)row * N + col], v);
                    } else {
                        if (act == 1) {
                            float xx = v + bias[col];
                            v = fmaxf(xx, 0.f) + log1pf(__expf(-fabsf(xx)));
                        }
                        C[(size_t)row * N + col] = v;
                    }
                }
            }
        }
    }
}

// ---------------- conv K=4 + SiLU ----------------
__global__ __launch_bounds__(256) void conv_silu_k(
    const float* __restrict__ proj, const float* __restrict__ cw,
    const float* __restrict__ cb, float* __restrict__ ucl)
{
    int idx = blockIdx.x * 256 + threadIdx.x;
    int t = idx >> 11, i = idx & 2047;
    float4 w = *(const float4*)(cw + i * 4);
    float acc = cb[i];
    if (t >= 3) acc += proj[(size_t)(t - 3) * 4096 + i] * w.x;
    if (t >= 2) acc += proj[(size_t)(t - 2) * 4096 + i] * w.y;
    if (t >= 1) acc += proj[(size_t)(t - 1) * 4096 + i] * w.z;
    acc += proj[(size_t)t * 4096 + i] * w.w;
    ucl[idx] = acc / (1.f + __expf(-acc));
}

// ---------------- rmsnorm dt/B/C ----------------
__global__ __launch_bounds__(128) void rmsnorm_dtbc_k(
    const float* __restrict__ ssm, const float* __restrict__ wdt,
    const float* __restrict__ wB, const float* __restrict__ wC,
    float* __restrict__ dtn, float* __restrict__ Bn, float* __restrict__ Cn)
{
    int warp = (blockIdx.x * blockDim.x + threadIdx.x) >> 5;
    int lane = threadIdx.x & 31;
    if (warp >= LL) return;
    const float* row = ssm + (size_t)warp * 96;

    float v0 = row[lane], v1 = row[lane + 32];
    float ss = v0 * v0 + v1 * v1;
#pragma unroll
    for (int o = 16; o; o >>= 1) ss += __shfl_xor_sync(~0u, ss, o);
    float r = rsqrtf(ss / 64.f + EPSV);
    dtn[warp * 64 + lane]      = v0 * r * wdt[lane];
    dtn[warp * 64 + lane + 32] = v1 * r * wdt[lane + 32];

    float b = (lane < 16) ? row[64 + lane] : 0.f;
    float sb = b * b;
#pragma unroll
    for (int o = 16; o; o >>= 1) sb += __shfl_xor_sync(~0u, sb, o);
    float rb = rsqrtf(sb / 16.f + EPSV);
    if (lane < 16) Bn[warp * 16 + lane] = b * rb * wB[lane];

    float c = (lane < 16) ? row[80 + lane] : 0.f;
    float sc = c * c;
#pragma unroll
    for (int o = 16; o; o >>= 1) sc += __shfl_xor_sync(~0u, sc, o);
    float rc = rsqrtf(sc / 16.f + EPSV);
    if (lane < 16) Cn[warp * 16 + lane] = c * rc * wC[lane];
}

// ---------------- scan pass A ----------------
__global__ __launch_bounds__(128) void scan_passA_k(
    const float* __restrict__ dtact, const float* __restrict__ ucl,
    const float* __restrict__ Bn, const float* __restrict__ A_log,
    float* __restrict__ chunkh, float* __restrict__ sumdt)
{
    __shared__ float Bs[CHSZ][NST];
    const int c = blockIdx.y;
    const int i = blockIdx.x * 128 + threadIdx.x;
    for (int idx = threadIdx.x; idx < CHSZ * NST; idx += 128)
        Bs[idx >> 4][idx & 15] = Bn[(size_t)(c * CHSZ + (idx >> 4)) * NST + (idx & 15)];
    __syncthreads();

    float Ai[NST];
#pragma unroll
    for (int n = 0; n < NST; n++) Ai[n] = -__expf(A_log[(size_t)i * NST + n]);
    bool geom = true;
#pragma unroll
    for (int n = 1; n < NST; n++) {
        float ex = Ai[0] * (float)(n + 1);
        if (fabsf(Ai[n] - ex) > 1e-3f * fabsf(ex)) geom = false;
    }

    float h[NST];
#pragma unroll
    for (int n = 0; n < NST; n++) h[n] = 0.f;
    float sdt = 0.f;

    if (geom) {
        const float a0 = Ai[0];
        for (int t = 0; t < CHSZ; t++) {
            int tg = c * CHSZ + t;
            float dtv = dtact[(size_t)tg * II + i];
            float uv  = ucl[(size_t)tg * II + i];
            sdt += dtv;
            float du = dtv * uv;
            float e1 = __expf(dtv * a0);
            float p = e1;
#pragma unroll
            for (int n = 0; n < NST; n++) {
                h[n] = h[n] * p + du * Bs[t][n];
                p *= e1;
            }
        }
    } else {
        for (int t = 0; t < CHSZ; t++) {
            int tg = c * CHSZ + t;
            float dtv = dtact[(size_t)tg * II + i];
            float uv  = ucl[(size_t)tg * II + i];
            sdt += dtv;
            float du = dtv * uv;
#pragma unroll
            for (int n = 0; n < NST; n++)
                h[n] = h[n] * __expf(dtv * Ai[n]) + du * Bs[t][n];
        }
    }
#pragma unroll
    for (int n = 0; n < NST; n++)
        chunkh[((size_t)c * II + i) * NST + n] = h[n];
    sumdt[c * II + i] = sdt;
}

// ---------------- scan pass B ----------------
__global__ __launch_bounds__(256) void scan_passB_k(
    const float* __restrict__ chunkh, const float* __restrict__ sumdt,
    const float* __restrict__ A_log, float* __restrict__ hstart)
{
    int idx = blockIdx.x * 256 + threadIdx.x;
    int i = idx >> 4;
    float A = -__expf(A_log[idx]);
    float h = 0.f;
    for (int c = 0; c < NCH; c++) {
        hstart[(size_t)c * (II * NST) + idx] = h;
        h = h * __expf(A * sumdt[c * II + i]) + chunkh[(size_t)c * (II * NST) + idx];
    }
}

// ---------------- scan pass C ----------------
__global__ __launch_bounds__(128) void scan_passC_k(
    const float* __restrict__ dtact, const float* __restrict__ ucl,
    const float* __restrict__ Bn, const float* __restrict__ Cn,
    const float* __restrict__ A_log, const float* __restrict__ hstart,
    const float* __restrict__ Dsk, const float* __restrict__ proj,
    float* __restrict__ mamba)
{
    __shared__ float Bs[CHSZ][NST];
    __shared__ float Cs[CHSZ][NST];
    const int c = blockIdx.y;
    const int i = blockIdx.x * 128 + threadIdx.x;
    for (int idx = threadIdx.x; idx < CHSZ * NST; idx += 128) {
        int t = idx >> 4, n = idx & 15;
        Bs[t][n] = Bn[(size_t)(c * CHSZ + t) * NST + n];
        Cs[t][n] = Cn[(size_t)(c * CHSZ + t) * NST + n];
    }
    __syncthreads();

    float Ai[NST];
#pragma unroll
    for (int n = 0; n < NST; n++) Ai[n] = -__expf(A_log[(size_t)i * NST + n]);
    bool geom = true;
#pragma unroll
    for (int n = 1; n < NST; n++) {
        float ex = Ai[0] * (float)(n + 1);
        if (fabsf(Ai[n] - ex) > 1e-3f * fabsf(ex)) geom = false;
    }

    float h[NST];
#pragma unroll
    for (int n = 0; n < NST; n++) h[n] = hstart[((size_t)c * II + i) * NST + n];
    const float Dv = Dsk[i];

    if (geom) {
        const float a0 = Ai[0];
        for (int t = 0; t < CHSZ; t++) {
            int tg = c * CHSZ + t;
            float dtv = dtact[(size_t)tg * II + i];
            float uv  = ucl[(size_t)tg * II + i];
            float du = dtv * uv;
            float e1 = __expf(dtv * a0);
            float p = e1;
            float y = 0.f;
#pragma unroll
            for (int n = 0; n < NST; n++) {
                h[n] = h[n] * p + du * Bs[t][n];
                y += h[n] * Cs[t][n];
                p *= e1;
            }
            float g = proj[(size_t)tg * 4096 + 2048 + i];
            float sg = g / (1.f + __expf(-g));
            mamba[(size_t)tg * II + i] = (y + uv * Dv) * sg;
        }
    } else {
        for (int t = 0; t < CHSZ; t++) {
            int tg = c * CHSZ + t;
            float dtv = dtact[(size_t)tg * II + i];
            float uv  = ucl[(size_t)tg * II + i];
            float du = dtv * uv;
            float y = 0.f;
#pragma unroll
            for (int n = 0; n < NST; n++) {
                h[n] = h[n] * __expf(dtv * Ai[n]) + du * Bs[t][n];
                y += h[n] * Cs[t][n];
            }
            float g = proj[(size_t)tg * 4096 + 2048 + i];
            float sg = g / (1.f + __expf(-g));
            mamba[(size_t)tg * II + i] = (y + uv * Dv) * sg;
        }
    }
}

// ---------------- RoPE ----------------
__global__ __launch_bounds__(256) void rope_q_k(
    const float* __restrict__ proj, float* __restrict__ qr)
{
    int idx = blockIdx.x * 256 + threadIdx.x;
    int t = idx >> 11, col = idx & 2047, d = col & 127;
    int j = d & 63;
    float ang = (float)t * __expf(-(float)j * 0.14391156831212787f);
    float s, c;
    sincosf(ang, &s, &c);
    float x = proj[(size_t)t * 4096 + col];
    float other = (d < 64) ? proj[(size_t)t * 4096 + col + 64]
                           : proj[(size_t)t * 4096 + col - 64];
    qr[idx] = (d < 64) ? (x * c - other * s) : (x * c + other * s);
}

__global__ __launch_bounds__(256) void rope_k_k(
    const float* __restrict__ klin, float* __restrict__ kr)
{
    int idx = blockIdx.x * 256 + threadIdx.x;
    int t = idx >> 9, col = idx & 511, d = col & 127;
    int j = d & 63;
    float ang = (float)t * __expf(-(float)j * 0.14391156831212787f);
    float s, c;
    sincosf(ang, &s, &c);
    float x = klin[(size_t)t * 512 + col];
    float other = (d < 64) ? klin[(size_t)t * 512 + col + 64]
                           : klin[(size_t)t * 512 + col - 64];
    kr[idx] = (d < 64) ? (x * c - other * s) : (x * c + other * s);
}

// ---------------- flash attention (FFMA2 inner loops) ----------------
__global__ __launch_bounds__(256) void attn_k(
    const float* __restrict__ qr, const float* __restrict__ kr,
    const float* __restrict__ vr, float* __restrict__ attn_out)
{
    extern __shared__ float smem[];
    float* Qs = smem;
    float* Ks = Qs + 8192;
    float* Vs = Ks + 8192;
    float* Ps = Vs + 8192;
    __shared__ float m_s[64], l_s[64], al_s[64];

    const int tid = threadIdx.x;
    const int q0 = blockIdx.x * 64;
    const int h = blockIdx.y;
    const int kvh = h >> 2;
    const float scale = 0.08838834764831845f;

    for (int i = tid * 4; i < 8192; i += 1024) {
        int r = i >> 7, d = i & 127;
        float4 q = *(const float4*)(qr + (size_t)(q0 + r) * 2048 + h * 128 + d);
        q.x *= scale; q.y *= scale; q.z *= scale; q.w *= scale;
        *(float4*)&Qs[i] = q;
    }
    if (tid < 64) { m_s[tid] = -1e30f; l_s[tid] = 0.f; al_s[tid] = 1.f; }

    const int sr = (tid >> 4) << 2;
    const int sc = (tid & 15) << 2;
    const int pc = (tid & 15) << 3;
    u64 O2[4][4];
#pragma unroll
    for (int i = 0; i < 4; i++)
#pragma unroll
        for (int jp = 0; jp < 4; jp++) O2[i][jp] = 0ull;

    __syncthreads();

    int wstart = q0 - 1024; if (wstart < 128) wstart = 128;

    for (int ti = 0; ti < 20; ti++) {
        int k0;
        if (ti < 2) { k0 = ti << 6; }
        else { k0 = wstart + ((ti - 2) << 6); if (k0 > q0) break; }

        for (int i = tid * 4; i < 8192; i += 1024) {
            int r = i >> 7, d = i & 127;
            size_t off = (size_t)(k0 + r) * 512 + kvh * 128 + d;
            *(float4*)&Ks[i] = *(const float4*)(kr + off);
            *(float4*)&Vs[i] = *(const float4*)(vr + off);
        }
        __syncthreads();

        // S = Q K^T via packed f32x2 (pack dim = head dim)
        u64 s2[4][4];
#pragma unroll
        for (int i = 0; i < 4; i++)
#pragma unroll
            for (int j = 0; j < 4; j++) s2[i][j] = 0ull;

        for (int kk = 0; kk < 128; kk += 4) {
            ulonglong2 a2[4], b2[4];
#pragma unroll
            for (int i = 0; i < 4; i++) a2[i] = *(const ulonglong2*)&Qs[(sr + i) * 128 + kk];
#pragma unroll
            for (int j = 0; j < 4; j++) b2[j] = *(const ulonglong2*)&Ks[(sc + j) * 128 + kk];
#pragma unroll
            for (int i = 0; i < 4; i++)
#pragma unroll
                for (int j = 0; j < 4; j++) {
                    fma2(s2[i][j], a2[i].x, b2[j].x);
                    fma2(s2[i][j], a2[i].y, b2[j].y);
                }
        }

        float s[4][4];
#pragma unroll
        for (int i = 0; i < 4; i++)
#pragma unroll
            for (int j = 0; j < 4; j++) {
                float2 t2 = unpack2(s2[i][j]);
                s[i][j] = t2.x + t2.y;
            }

#pragma unroll
        for (int i = 0; i < 4; i++) {
            int qi = q0 + sr + i;
#pragma unroll
            for (int j = 0; j < 4; j++) {
                int ki = k0 + sc + j;
                bool ok = (ki <= qi) && (((qi - ki) <= 1024) || (ki < 128));
                if (!ok) s[i][j] = -1e30f;
            }
        }

        float rmax[4];
#pragma unroll
        for (int i = 0; i < 4; i++)
            rmax[i] = fmaxf(fmaxf(s[i][0], s[i][1]), fmaxf(s[i][2], s[i][3]));
#pragma unroll
        for (int o = 1; o < 16; o <<= 1)
#pragma unroll
            for (int i = 0; i < 4; i++)
                rmax[i] = fmaxf(rmax[i], __shfl_xor_sync(~0u, rmax[i], o));

        float mo[4], mn[4], rs[4];
#pragma unroll
        for (int i = 0; i < 4; i++) {
            mo[i] = m_s[sr + i];
            mn[i] = fmaxf(mo[i], rmax[i]);
            rs[i] = 0.f;
        }
#pragma unroll
        for (int i = 0; i < 4; i++)
#pragma unroll
            for (int j = 0; j < 4; j++) {
                float p = __expf(s[i][j] - mn[i]);
                Ps[(sr + i) * 64 + sc + j] = p;
                rs[i] += p;
            }
#pragma unroll
        for (int o = 1; o < 16; o <<= 1)
#pragma unroll
            for (int i = 0; i < 4; i++)
                rs[i] += __shfl_xor_sync(~0u, rs[i], o);

        if ((tid & 15) == 0) {
#pragma unroll
            for (int i = 0; i < 4; i++) {
                float al = __expf(mo[i] - mn[i]);
                al_s[sr + i] = al;
                l_s[sr + i] = l_s[sr + i] * al + rs[i];
                m_s[sr + i] = mn[i];
            }
        }
        __syncthreads();

#pragma unroll
        for (int i = 0; i < 4; i++) {
            u64 al2 = pack2(al_s[sr + i], al_s[sr + i]);
#pragma unroll
            for (int jp = 0; jp < 4; jp++) mul2(O2[i][jp], al2);
        }

        // O += P V via packed f32x2 (pack dim = head-dim cols)
        for (int cix = 0; cix < 64; cix++) {
            ulonglong2 v0 = *(const ulonglong2*)&Vs[cix * 128 + pc];
            ulonglong2 v1 = *(const ulonglong2*)&Vs[cix * 128 + pc + 4];
#pragma unroll
            for (int i = 0; i < 4; i++) {
                float p = Ps[(sr + i) * 64 + cix];
                u64 p2 = pack2(p, p);
                fma2(O2[i][0], p2, v0.x);
                fma2(O2[i][1], p2, v0.y);
                fma2(O2[i][2], p2, v1.x);
                fma2(O2[i][3], p2, v1.y);
            }
        }
        __syncthreads();
    }

#pragma unroll
    for (int i = 0; i < 4; i++) {
        float inv = 1.f / l_s[sr + i];
        float2 o0 = unpack2(O2[i][0]);
        float2 o1 = unpack2(O2[i][1]);
        float2 o2 = unpack2(O2[i][2]);
        float2 o3 = unpack2(O2[i][3]);
        float4 w0 = make_float4(o0.x * inv, o0.y * inv, o1.x * inv, o1.y * inv);
        float4 w1 = make_float4(o2.x * inv, o2.y * inv, o3.x * inv, o3.y * inv);
        float* dst = attn_out + (size_t)(q0 + sr + i) * 2048 + h * 128 + pc;
        *(float4*)dst = w0;
        *(float4*)(dst + 4) = w1;
    }
}

// ---------------- fuse norms ----------------
__global__ __launch_bounds__(256) void fuse_norm_k(
    const float* __restrict__ attn, const float* __restrict__ mamba,
    const float* __restrict__ wa, const float* __restrict__ wm,
    float* __restrict__ fused)
{
    __shared__ float sh[18];
    int t = blockIdx.x, tid = threadIdx.x;
    float av[8], mv[8];
    float sa = 0.f, sm = 0.f;
#pragma unroll
    for (int k = 0; k < 8; k++) {
        int col = tid + k * 256;
        av[k] = attn[(size_t)t * II + col];
        mv[k] = mamba[(size_t)t * II + col];
        sa += av[k] * av[k];
        sm += mv[k] * mv[k];
    }
#pragma unroll
    for (int o = 16; o; o >>= 1) {
        sa += __shfl_xor_sync(~0u, sa, o);
        sm += __shfl_xor_sync(~0u, sm, o);
    }
    int w = tid >> 5;
    if ((tid & 31) == 0) { sh[w] = sa; sh[8 + w] = sm; }
    __syncthreads();
    if (tid == 0) {
        float ta = 0.f, tm = 0.f;
        for (int k = 0; k < 8; k++) { ta += sh[k]; tm += sh[8 + k]; }
        sh[16] = ta; sh[17] = tm;
    }
    __syncthreads();
    float ra = rsqrtf(sh[16] / (float)II + EPSV);
    float rm = rsqrtf(sh[17] / (float)II + EPSV);
#pragma unroll
    for (int k = 0; k < 8; k++) {
        int col = tid + k * 256;
        fused[(size_t)t * II + col] = 0.5f * (av[k] * ra * wa[col] + mv[k] * rm * wm[col]);
    }
}

// ---------------- host ----------------
extern "C" void kernel_launch(void* const* d_in, const int* in_sizes, int n_in,
                              void* d_out, int out_size)
{
    const float* x          = (const float*)d_in[0];
    const float* in_proj_w  = (const float*)d_in[1];
    const float* k_proj_w   = (const float*)d_in[2];
    const float* v_proj_w   = (const float*)d_in[3];
    const float* conv_w     = (const float*)d_in[4];
    const float* conv_b     = (const float*)d_in[5];
    const float* x_proj_w   = (const float*)d_in[6];
    const float* dt_proj_w  = (const float*)d_in[7];
    const float* dt_proj_b  = (const float*)d_in[8];
    const float* A_log      = (const float*)d_in[9];
    const float* D_skip     = (const float*)d_in[10];
    const float* dt_ln_w    = (const float*)d_in[11];
    const float* B_ln_w     = (const float*)d_in[12];
    const float* C_ln_w     = (const float*)d_in[13];
    const float* attn_ln_w  = (const float*)d_in[14];
    const float* mamba_ln_w = (const float*)d_in[15];
    const float* out_proj_w = (const float*)d_in[16];
    float* out = (float*)d_out;

    float *proj, *klin, *vlin, *ucl, *ssm, *dtn, *Bn, *Cn, *dtact;
    float *chunkh, *sumdt, *hstart, *mamba, *qr, *kr, *attn, *fused;
    cudaGetSymbolAddress((void**)&proj,   g_proj);
    cudaGetSymbolAddress((void**)&klin,   g_klin);
    cudaGetSymbolAddress((void**)&vlin,   g_vlin);
    cudaGetSymbolAddress((void**)&ucl,    g_ucl);
    cudaGetSymbolAddress((void**)&ssm,    g_ssm);
    cudaGetSymbolAddress((void**)&dtn,    g_dtn);
    cudaGetSymbolAddress((void**)&Bn,     g_Bn);
    cudaGetSymbolAddress((void**)&Cn,     g_Cn);
    cudaGetSymbolAddress((void**)&dtact,  g_dtact);
    cudaGetSymbolAddress((void**)&chunkh, g_chunkh);
    cudaGetSymbolAddress((void**)&sumdt,  g_sumdt);
    cudaGetSymbolAddress((void**)&hstart, g_hstart);
    cudaGetSymbolAddress((void**)&mamba,  g_mamba);
    cudaGetSymbolAddress((void**)&qr,     g_qr);
    cudaGetSymbolAddress((void**)&kr,     g_kr);
    cudaGetSymbolAddress((void**)&attn,   g_attn);
    cudaGetSymbolAddress((void**)&fused,  g_fused);

    // zero split-K accumulation targets
    cudaMemsetAsync(klin, 0, (size_t)LL * 512 * sizeof(float));
    cudaMemsetAsync(vlin, 0, (size_t)LL * 512 * sizeof(float));
    cudaMemsetAsync(ssm,  0, (size_t)LL * 96 * sizeof(float));

    // projections
    gemm_k<<<dim3(32, 16, 1), 256>>>(x, in_proj_w, proj, LL, 4096, DD, nullptr, 0, 1);
    gemm_k<<<dim3(4, 16, 4), 256>>>(x, k_proj_w, klin, LL, 512, DD, nullptr, 0, 4);
    gemm_k<<<dim3(4, 16, 4), 256>>>(x, v_proj_w, vlin, LL, 512, DD, nullptr, 0, 4);

    // mamba branch
    conv_silu_k<<<LL * II / 256, 256>>>(proj, conv_w, conv_b, ucl);
    gemm_k<<<dim3(1, 16, 8), 256>>>(ucl, x_proj_w, ssm, LL, 96, II, nullptr, 0, 8);
    rmsnorm_dtbc_k<<<512, 128>>>(ssm, dt_ln_w, B_ln_w, C_ln_w, dtn, Bn, Cn);
    gemm_k<<<dim3(16, 16, 1), 256>>>(dtn, dt_proj_w, dtact, LL, II, TSRD, dt_proj_b, 1, 1);
    scan_passA_k<<<dim3(II / 128, NCH), 128>>>(dtact, ucl, Bn, A_log, chunkh, sumdt);
    scan_passB_k<<<(II * NST) / 256, 256>>>(chunkh, sumdt, A_log, hstart);
    scan_passC_k<<<dim3(II / 128, NCH), 128>>>(dtact, ucl, Bn, Cn, A_log, hstart,
                                               D_skip, proj, mamba);

    // attention branch
    rope_q_k<<<LL * II / 256, 256>>>(proj, qr);
    rope_k_k<<<LL * 512 / 256, 256>>>(klin, kr);
    size_t smem = (size_t)(3 * 8192 + 4096) * sizeof(float);
    cudaFuncSetAttribute(attn_k, cudaFuncAttributeMaxDynamicSharedMemorySize, (int)smem);
    attn_k<<<dim3(LL / 64, HQ), 256, smem>>>(qr, kr, vlin, attn);

    // fuse + out projection
    fuse_norm_k<<<LL, 256>>>(attn, mamba, attn_ln_w, mamba_ln_w, fused);
    gemm_k<<<dim3(8, 16, 1), 256>>>(fused, out_proj_w, out, LL, DD, II, nullptr, 0, 1);
}

// round 11
// speedup vs baseline: 1.4110x; 1.0740x over previous
#include <cuda_runtime.h>
#include <math.h>
#include <stdint.h>

// ---------------- dims ----------------
#define LL   2048
#define DD   1024
#define II   2048
#define NST  16
#define TSRD 64
#define HQ   16
#define NCH  32
#define CHSZ 64
#define EPSV 1e-6f

typedef unsigned long long u64;

// ---------------- packed f32x2 helpers ----------------
__device__ __forceinline__ u64 pack2(float lo, float hi) {
    u64 r; asm("mov.b64 %0, {%1, %2};" : "=l"(r) : "f"(lo), "f"(hi)); return r;
}
__device__ __forceinline__ float2 unpack2(u64 v) {
    float2 r; asm("mov.b64 {%0, %1}, %2;" : "=f"(r.x), "=f"(r.y) : "l"(v)); return r;
}
__device__ __forceinline__ void fma2(u64& d, u64 a, u64 b) {
    asm("fma.rn.f32x2 %0, %1, %2, %0;" : "+l"(d) : "l"(a), "l"(b));
}
__device__ __forceinline__ void mul2(u64& d, u64 a) {
    asm("mul.rn.f32x2 %0, %0, %1;" : "+l"(d) : "l"(a));
}

// ---------------- scratch ----------------
__device__ float g_proj [LL * 2 * II];
__device__ float g_klin [LL * 512];
__device__ float g_vlin [LL * 512];
__device__ float g_ucl  [LL * II];
__device__ float g_ssm  [LL * 96];
__device__ float g_dtn  [LL * TSRD];
__device__ float g_Bn   [LL * NST];
__device__ float g_Cn   [LL * NST];
__device__ float g_dtact[LL * II];
__device__ float g_chunkh[NCH * II * NST];
__device__ float g_sumdt [NCH * II];
__device__ float g_hstart[NCH * II * NST];
__device__ float g_mamba[LL * II];
__device__ float g_qr   [LL * II];
__device__ float g_kr   [LL * 512];
__device__ float g_attn [LL * II];
__device__ float g_fused[LL * II];

// ---------------- cp.async helpers ----------------
__device__ __forceinline__ void cp_async16(void* smem_dst, const void* gmem_src, int src_bytes) {
    uint32_t saddr = (uint32_t)__cvta_generic_to_shared(smem_dst);
    asm volatile("cp.async.cg.shared.global [%0], [%1], 16, %2;"
                 :: "r"(saddr), "l"(gmem_src), "r"(src_bytes));
}
__device__ __forceinline__ void cp_commit() {
    asm volatile("cp.async.commit_group;");
}
__device__ __forceinline__ void cp_wait0() {
    asm volatile("cp.async.wait_group 0;");
}

// ---------------- SGEMM: 128x128x8, 8x8/thread, cp.async DB + FFMA2 inner ----------------
__global__ __launch_bounds__(256) void gemm_k(
    const float* __restrict__ A, const float* __restrict__ B, float* __restrict__ C,
    int M, int N, int K, const float* __restrict__ bias, int act, int nsplit)
{
    __shared__ float As[2][8][128];
    __shared__ float Bs[2][8][128];
    const int tid = threadIdx.x;
    const int m0 = blockIdx.y * 128;
    const int n0 = blockIdx.x * 128;
    const int klen = K / nsplit;
    const int ks = blockIdx.z * klen;
    const int nk = klen / 8;
    const int tr = (tid >> 4) * 8;
    const int tc = (tid & 15) * 8;

    u64 acc2[8][4];
#pragma unroll
    for (int i = 0; i < 8; i++)
#pragma unroll
        for (int jp = 0; jp < 4; jp++) acc2[i][jp] = 0ull;

    const int la_m = tid >> 1;
    const int la_k = (tid & 1) * 4;
    const int lb_k = tid >> 5;
    const int lb_n = (tid & 31) * 4;

    const float* Ap = A + (size_t)(m0 + la_m) * K + ks + la_k;
    const int gn = n0 + lb_n;
    const float* Bp = B + (size_t)(ks + lb_k) * N + gn;
    int bbytes = (N - gn) * 4;
    if (bbytes < 0) bbytes = 0;
    if (bbytes > 16) bbytes = 16;

    {
        float4 av = *(const float4*)(Ap);
        As[0][la_k + 0][la_m] = av.x;
        As[0][la_k + 1][la_m] = av.y;
        As[0][la_k + 2][la_m] = av.z;
        As[0][la_k + 3][la_m] = av.w;
        if (bbytes < 16) {
            float* d = &Bs[0][lb_k][lb_n];
            d[0] = d[1] = d[2] = d[3] = 0.f;
        }
        cp_async16(&Bs[0][lb_k][lb_n], Bp, bbytes);
        cp_commit();
        cp_wait0();
    }
    __syncthreads();

    for (int kt = 0; kt < nk; kt++) {
        const int cur = kt & 1, nxt = cur ^ 1;
        const bool have = (kt + 1 < nk);
        float4 avn;
        if (have) {
            avn = *(const float4*)(Ap + (kt + 1) * 8);
            if (bbytes < 16) {
                float* d = &Bs[nxt][lb_k][lb_n];
                d[0] = d[1] = d[2] = d[3] = 0.f;
            }
            cp_async16(&Bs[nxt][lb_k][lb_n], Bp + (size_t)(kt + 1) * 8 * N, bbytes);
            cp_commit();
        }

#pragma unroll
        for (int kk = 0; kk < 8; kk++) {
            float a[8];
            *(float4*)&a[0] = *(const float4*)&As[cur][kk][tr];
            *(float4*)&a[4] = *(const float4*)&As[cur][kk][tr + 4];
            ulonglong2 bq0 = *(const ulonglong2*)&Bs[cur][kk][tc];
            ulonglong2 bq1 = *(const ulonglong2*)&Bs[cur][kk][tc + 4];
            u64 b2[4] = { bq0.x, bq0.y, bq1.x, bq1.y };
#pragma unroll
            for (int i = 0; i < 8; i++) {
                u64 a2 = pack2(a[i], a[i]);
#pragma unroll
                for (int jp = 0; jp < 4; jp++)
                    fma2(acc2[i][jp], a2, b2[jp]);
            }
        }

        if (have) {
            As[nxt][la_k + 0][la_m] = avn.x;
            As[nxt][la_k + 1][la_m] = avn.y;
            As[nxt][la_k + 2][la_m] = avn.z;
            As[nxt][la_k + 3][la_m] = avn.w;
            cp_wait0();
        }
        __syncthreads();
    }

#pragma unroll
    for (int i = 0; i < 8; i++) {
        int row = m0 + tr + i;
#pragma unroll
        for (int jp = 0; jp < 4; jp++) {
            float2 v2 = unpack2(acc2[i][jp]);
            float vv[2] = { v2.x, v2.y };
#pragma unroll
            for (int e = 0; e < 2; e++) {
                int col = n0 + tc + jp * 2 + e;
                if (col < N) {
                    float v = vv[e];
                    if (nsplit > 1) {
                        atomicAdd(&C[(size_t)row * N + col], v);
                    } else {
                        if (act == 1) {
                            float xx = v + bias[col];
                            v = fmaxf(xx, 0.f) + log1pf(__expf(-fabsf(xx)));
                        }
                        C[(size_t)row * N + col] = v;
                    }
                }
            }
        }
    }
}

// ---------------- conv K=4 + SiLU ----------------
__global__ __launch_bounds__(256) void conv_silu_k(
    const float* __restrict__ proj, const float* __restrict__ cw,
    const float* __restrict__ cb, float* __restrict__ ucl)
{
    int idx = blockIdx.x * 256 + threadIdx.x;
    int t = idx >> 11, i = idx & 2047;
    float4 w = *(const float4*)(cw + i * 4);
    float acc = cb[i];
    if (t >= 3) acc += proj[(size_t)(t - 3) * 4096 + i] * w.x;
    if (t >= 2) acc += proj[(size_t)(t - 2) * 4096 + i] * w.y;
    if (t >= 1) acc += proj[(size_t)(t - 1) * 4096 + i] * w.z;
    acc += proj[(size_t)t * 4096 + i] * w.w;
    ucl[idx] = acc / (1.f + __expf(-acc));
}

// ---------------- rmsnorm dt/B/C ----------------
__global__ __launch_bounds__(128) void rmsnorm_dtbc_k(
    const float* __restrict__ ssm, const float* __restrict__ wdt,
    const float* __restrict__ wB, const float* __restrict__ wC,
    float* __restrict__ dtn, float* __restrict__ Bn, float* __restrict__ Cn)
{
    int warp = (blockIdx.x * blockDim.x + threadIdx.x) >> 5;
    int lane = threadIdx.x & 31;
    if (warp >= LL) return;
    const float* row = ssm + (size_t)warp * 96;

    float v0 = row[lane], v1 = row[lane + 32];
    float ss = v0 * v0 + v1 * v1;
#pragma unroll
    for (int o = 16; o; o >>= 1) ss += __shfl_xor_sync(~0u, ss, o);
    float r = rsqrtf(ss / 64.f + EPSV);
    dtn[warp * 64 + lane]      = v0 * r * wdt[lane];
    dtn[warp * 64 + lane + 32] = v1 * r * wdt[lane + 32];

    float b = (lane < 16) ? row[64 + lane] : 0.f;
    float sb = b * b;
#pragma unroll
    for (int o = 16; o; o >>= 1) sb += __shfl_xor_sync(~0u, sb, o);
    float rb = rsqrtf(sb / 16.f + EPSV);
    if (lane < 16) Bn[warp * 16 + lane] = b * rb * wB[lane];

    float c = (lane < 16) ? row[80 + lane] : 0.f;
    float sc = c * c;
#pragma unroll
    for (int o = 16; o; o >>= 1) sc += __shfl_xor_sync(~0u, sc, o);
    float rc = rsqrtf(sc / 16.f + EPSV);
    if (lane < 16) Cn[warp * 16 + lane] = c * rc * wC[lane];
}

// ---------------- scan pass A (256-thread blocks) ----------------
__global__ __launch_bounds__(256) void scan_passA_k(
    const float* __restrict__ dtact, const float* __restrict__ ucl,
    const float* __restrict__ Bn, const float* __restrict__ A_log,
    float* __restrict__ chunkh, float* __restrict__ sumdt)
{
    __shared__ float Bs[CHSZ][NST];
    const int c = blockIdx.y;
    const int i = blockIdx.x * 256 + threadIdx.x;
    for (int idx = threadIdx.x; idx < CHSZ * NST; idx += 256)
        Bs[idx >> 4][idx & 15] = Bn[(size_t)(c * CHSZ + (idx >> 4)) * NST + (idx & 15)];
    __syncthreads();

    float Ai[NST];
#pragma unroll
    for (int n = 0; n < NST; n++) Ai[n] = -__expf(A_log[(size_t)i * NST + n]);
    bool geom = true;
#pragma unroll
    for (int n = 1; n < NST; n++) {
        float ex = Ai[0] * (float)(n + 1);
        if (fabsf(Ai[n] - ex) > 1e-3f * fabsf(ex)) geom = false;
    }

    float h[NST];
#pragma unroll
    for (int n = 0; n < NST; n++) h[n] = 0.f;
    float sdt = 0.f;

    if (geom) {
        const float a0 = Ai[0];
        for (int t = 0; t < CHSZ; t++) {
            int tg = c * CHSZ + t;
            float dtv = dtact[(size_t)tg * II + i];
            float uv  = ucl[(size_t)tg * II + i];
            sdt += dtv;
            float du = dtv * uv;
            float e1 = __expf(dtv * a0);
            float p = e1;
#pragma unroll
            for (int n = 0; n < NST; n++) {
                h[n] = h[n] * p + du * Bs[t][n];
                p *= e1;
            }
        }
    } else {
        for (int t = 0; t < CHSZ; t++) {
            int tg = c * CHSZ + t;
            float dtv = dtact[(size_t)tg * II + i];
            float uv  = ucl[(size_t)tg * II + i];
            sdt += dtv;
            float du = dtv * uv;
#pragma unroll
            for (int n = 0; n < NST; n++)
                h[n] = h[n] * __expf(dtv * Ai[n]) + du * Bs[t][n];
        }
    }
#pragma unroll
    for (int n = 0; n < NST; n++)
        chunkh[((size_t)c * II + i) * NST + n] = h[n];
    sumdt[c * II + i] = sdt;
}

// ---------------- scan pass B ----------------
__global__ __launch_bounds__(256) void scan_passB_k(
    const float* __restrict__ chunkh, const float* __restrict__ sumdt,
    const float* __restrict__ A_log, float* __restrict__ hstart)
{
    int idx = blockIdx.x * 256 + threadIdx.x;
    int i = idx >> 4;
    float A = -__expf(A_log[idx]);
    float h = 0.f;
    for (int c = 0; c < NCH; c++) {
        hstart[(size_t)c * (II * NST) + idx] = h;
        h = h * __expf(A * sumdt[c * II + i]) + chunkh[(size_t)c * (II * NST) + idx];
    }
}

// ---------------- scan pass C (256-thread blocks) ----------------
__global__ __launch_bounds__(256) void scan_passC_k(
    const float* __restrict__ dtact, const float* __restrict__ ucl,
    const float* __restrict__ Bn, const float* __restrict__ Cn,
    const float* __restrict__ A_log, const float* __restrict__ hstart,
    const float* __restrict__ Dsk, const float* __restrict__ proj,
    float* __restrict__ mamba)
{
    __shared__ float Bs[CHSZ][NST];
    __shared__ float Cs[CHSZ][NST];
    const int c = blockIdx.y;
    const int i = blockIdx.x * 256 + threadIdx.x;
    for (int idx = threadIdx.x; idx < CHSZ * NST; idx += 256) {
        int t = idx >> 4, n = idx & 15;
        Bs[t][n] = Bn[(size_t)(c * CHSZ + t) * NST + n];
        Cs[t][n] = Cn[(size_t)(c * CHSZ + t) * NST + n];
    }
    __syncthreads();

    float Ai[NST];
#pragma unroll
    for (int n = 0; n < NST; n++) Ai[n] = -__expf(A_log[(size_t)i * NST + n]);
    bool geom = true;
#pragma unroll
    for (int n = 1; n < NST; n++) {
        float ex = Ai[0] * (float)(n + 1);
        if (fabsf(Ai[n] - ex) > 1e-3f * fabsf(ex)) geom = false;
    }

    float h[NST];
#pragma unroll
    for (int n = 0; n < NST; n++) h[n] = hstart[((size_t)c * II + i) * NST + n];
    const float Dv = Dsk[i];

    if (geom) {
        const float a0 = Ai[0];
        for (int t = 0; t < CHSZ; t++) {
            int tg = c * CHSZ + t;
            float dtv = dtact[(size_t)tg * II + i];
            float uv  = ucl[(size_t)tg * II + i];
            float du = dtv * uv;
            float e1 = __expf(dtv * a0);
            float p = e1;
            float y = 0.f;
#pragma unroll
            for (int n = 0; n < NST; n++) {
                h[n] = h[n] * p + du * Bs[t][n];
                y += h[n] * Cs[t][n];
                p *= e1;
            }
            float g = proj[(size_t)tg * 4096 + 2048 + i];
            float sg = g / (1.f + __expf(-g));
            mamba[(size_t)tg * II + i] = (y + uv * Dv) * sg;
        }
    } else {
        for (int t = 0; t < CHSZ; t++) {
            int tg = c * CHSZ + t;
            float dtv = dtact[(size_t)tg * II + i];
            float uv  = ucl[(size_t)tg * II + i];
            float du = dtv * uv;
            float y = 0.f;
#pragma unroll
            for (int n = 0; n < NST; n++) {
                h[n] = h[n] * __expf(dtv * Ai[n]) + du * Bs[t][n];
                y += h[n] * Cs[t][n];
            }
            float g = proj[(size_t)tg * 4096 + 2048 + i];
            float sg = g / (1.f + __expf(-g));
            mamba[(size_t)tg * II + i] = (y + uv * Dv) * sg;
        }
    }
}

// ---------------- RoPE ----------------
__global__ __launch_bounds__(256) void rope_q_k(
    const float* __restrict__ proj, float* __restrict__ qr)
{
    int idx = blockIdx.x * 256 + threadIdx.x;
    int t = idx >> 11, col = idx & 2047, d = col & 127;
    int j = d & 63;
    float ang = (float)t * __expf(-(float)j * 0.14391156831212787f);
    float s, c;
    sincosf(ang, &s, &c);
    float x = proj[(size_t)t * 4096 + col];
    float other = (d < 64) ? proj[(size_t)t * 4096 + col + 64]
                           : proj[(size_t)t * 4096 + col - 64];
    qr[idx] = (d < 64) ? (x * c - other * s) : (x * c + other * s);
}

__global__ __launch_bounds__(256) void rope_k_k(
    const float* __restrict__ klin, float* __restrict__ kr)
{
    int idx = blockIdx.x * 256 + threadIdx.x;
    int t = idx >> 9, col = idx & 511, d = col & 127;
    int j = d & 63;
    float ang = (float)t * __expf(-(float)j * 0.14391156831212787f);
    float s, c;
    sincosf(ang, &s, &c);
    float x = klin[(size_t)t * 512 + col];
    float other = (d < 64) ? klin[(size_t)t * 512 + col + 64]
                           : klin[(size_t)t * 512 + col - 64];
    kr[idx] = (d < 64) ? (x * c - other * s) : (x * c + other * s);
}

// ---------------- flash attention (FFMA2 inner loops) ----------------
__global__ __launch_bounds__(256) void attn_k(
    const float* __restrict__ qr, const float* __restrict__ kr,
    const float* __restrict__ vr, float* __restrict__ attn_out)
{
    extern __shared__ float smem[];
    float* Qs = smem;
    float* Ks = Qs + 8192;
    float* Vs = Ks + 8192;
    float* Ps = Vs + 8192;
    __shared__ float m_s[64], l_s[64], al_s[64];

    const int tid = threadIdx.x;
    const int q0 = blockIdx.x * 64;
    const int h = blockIdx.y;
    const int kvh = h >> 2;
    const float scale = 0.08838834764831845f;

    for (int i = tid * 4; i < 8192; i += 1024) {
        int r = i >> 7, d = i & 127;
        float4 q = *(const float4*)(qr + (size_t)(q0 + r) * 2048 + h * 128 + d);
        q.x *= scale; q.y *= scale; q.z *= scale; q.w *= scale;
        *(float4*)&Qs[i] = q;
    }
    if (tid < 64) { m_s[tid] = -1e30f; l_s[tid] = 0.f; al_s[tid] = 1.f; }

    const int sr = (tid >> 4) << 2;
    const int sc = (tid & 15) << 2;
    const int pc = (tid & 15) << 3;
    u64 O2[4][4];
#pragma unroll
    for (int i = 0; i < 4; i++)
#pragma unroll
        for (int jp = 0; jp < 4; jp++) O2[i][jp] = 0ull;

    __syncthreads();

    int wstart = q0 - 1024; if (wstart < 128) wstart = 128;

    for (int ti = 0; ti < 20; ti++) {
        int k0;
        if (ti < 2) { k0 = ti << 6; }
        else { k0 = wstart + ((ti - 2) << 6); if (k0 > q0) break; }

        for (int i = tid * 4; i < 8192; i += 1024) {
            int r = i >> 7, d = i & 127;
            size_t off = (size_t)(k0 + r) * 512 + kvh * 128 + d;
            *(float4*)&Ks[i] = *(const float4*)(kr + off);
            *(float4*)&Vs[i] = *(const float4*)(vr + off);
        }
        __syncthreads();

        u64 s2[4][4];
#pragma unroll
        for (int i = 0; i < 4; i++)
#pragma unroll
            for (int j = 0; j < 4; j++) s2[i][j] = 0ull;

        for (int kk = 0; kk < 128; kk += 4) {
            ulonglong2 a2[4], b2[4];
#pragma unroll
            for (int i = 0; i < 4; i++) a2[i] = *(const ulonglong2*)&Qs[(sr + i) * 128 + kk];
#pragma unroll
            for (int j = 0; j < 4; j++) b2[j] = *(const ulonglong2*)&Ks[(sc + j) * 128 + kk];
#pragma unroll
            for (int i = 0; i < 4; i++)
#pragma unroll
                for (int j = 0; j < 4; j++) {
                    fma2(s2[i][j], a2[i].x, b2[j].x);
                    fma2(s2[i][j], a2[i].y, b2[j].y);
                }
        }

        float s[4][4];
#pragma unroll
        for (int i = 0; i < 4; i++)
#pragma unroll
            for (int j = 0; j < 4; j++) {
                float2 t2 = unpack2(s2[i][j]);
                s[i][j] = t2.x + t2.y;
            }

#pragma unroll
        for (int i = 0; i < 4; i++) {
            int qi = q0 + sr + i;
#pragma unroll
            for (int j = 0; j < 4; j++) {
                int ki = k0 + sc + j;
                bool ok = (ki <= qi) && (((qi - ki) <= 1024) || (ki < 128));
                if (!ok) s[i][j] = -1e30f;
            }
        }

        float rmax[4];
#pragma unroll
        for (int i = 0; i < 4; i++)
            rmax[i] = fmaxf(fmaxf(s[i][0], s[i][1]), fmaxf(s[i][2], s[i][3]));
#pragma unroll
        for (int o = 1; o < 16; o <<= 1)
#pragma unroll
            for (int i = 0; i < 4; i++)
                rmax[i] = fmaxf(rmax[i], __shfl_xor_sync(~0u, rmax[i], o));

        float mo[4], mn[4], rs[4];
#pragma unroll
        for (int i = 0; i < 4; i++) {
            mo[i] = m_s[sr + i];
            mn[i] = fmaxf(mo[i], rmax[i]);
            rs[i] = 0.f;
        }
#pragma unroll
        for (int i = 0; i < 4; i++)
#pragma unroll
            for (int j = 0; j < 4; j++) {
                float p = __expf(s[i][j] - mn[i]);
                Ps[(sr + i) * 64 + sc + j] = p;
                rs[i] += p;
            }
#pragma unroll
        for (int o = 1; o < 16; o <<= 1)
#pragma unroll
            for (int i = 0; i < 4; i++)
                rs[i] += __shfl_xor_sync(~0u, rs[i], o);

        if ((tid & 15) == 0) {
#pragma unroll
            for (int i = 0; i < 4; i++) {
                float al = __expf(mo[i] - mn[i]);
                al_s[sr + i] = al;
                l_s[sr + i] = l_s[sr + i] * al + rs[i];
                m_s[sr + i] = mn[i];
            }
        }
        __syncthreads();

#pragma unroll
        for (int i = 0; i < 4; i++) {
            u64 al2 = pack2(al_s[sr + i], al_s[sr + i]);
#pragma unroll
            for (int jp = 0; jp < 4; jp++) mul2(O2[i][jp], al2);
        }

        for (int cix = 0; cix < 64; cix++) {
            ulonglong2 v0 = *(const ulonglong2*)&Vs[cix * 128 + pc];
            ulonglong2 v1 = *(const ulonglong2*)&Vs[cix * 128 + pc + 4];
#pragma unroll
            for (int i = 0; i < 4; i++) {
                float p = Ps[(sr + i) * 64 + cix];
                u64 p2 = pack2(p, p);
                fma2(O2[i][0], p2, v0.x);
                fma2(O2[i][1], p2, v0.y);
                fma2(O2[i][2], p2, v1.x);
                fma2(O2[i][3], p2, v1.y);
            }
        }
        __syncthreads();
    }

#pragma unroll
    for (int i = 0; i < 4; i++) {
        float inv = 1.f / l_s[sr + i];
        float2 o0 = unpack2(O2[i][0]);
        float2 o1 = unpack2(O2[i][1]);
        float2 o2 = unpack2(O2[i][2]);
        float2 o3 = unpack2(O2[i][3]);
        float4 w0 = make_float4(o0.x * inv, o0.y * inv, o1.x * inv, o1.y * inv);
        float4 w1 = make_float4(o2.x * inv, o2.y * inv, o3.x * inv, o3.y * inv);
        float* dst = attn_out + (size_t)(q0 + sr + i) * 2048 + h * 128 + pc;
        *(float4*)dst = w0;
        *(float4*)(dst + 4) = w1;
    }
}

// ---------------- fuse norms ----------------
__global__ __launch_bounds__(256) void fuse_norm_k(
    const float* __restrict__ attn, const float* __restrict__ mamba,
    const float* __restrict__ wa, const float* __restrict__ wm,
    float* __restrict__ fused)
{
    __shared__ float sh[18];
    int t = blockIdx.x, tid = threadIdx.x;
    float av[8], mv[8];
    float sa = 0.f, sm = 0.f;
#pragma unroll
    for (int k = 0; k < 8; k++) {
        int col = tid + k * 256;
        av[k] = attn[(size_t)t * II + col];
        mv[k] = mamba[(size_t)t * II + col];
        sa += av[k] * av[k];
        sm += mv[k] * mv[k];
    }
#pragma unroll
    for (int o = 16; o; o >>= 1) {
        sa += __shfl_xor_sync(~0u, sa, o);
        sm += __shfl_xor_sync(~0u, sm, o);
    }
    int w = tid >> 5;
    if ((tid & 31) == 0) { sh[w] = sa; sh[8 + w] = sm; }
    __syncthreads();
    if (tid == 0) {
        float ta = 0.f, tm = 0.f;
        for (int k = 0; k < 8; k++) { ta += sh[k]; tm += sh[8 + k]; }
        sh[16] = ta; sh[17] = tm;
    }
    __syncthreads();
    float ra = rsqrtf(sh[16] / (float)II + EPSV);
    float rm = rsqrtf(sh[17] / (float)II + EPSV);
#pragma unroll
    for (int k = 0; k < 8; k++) {
        int col = tid + k * 256;
        fused[(size_t)t * II + col] = 0.5f * (av[k] * ra * wa[col] + mv[k] * rm * wm[col]);
    }
}

// ---------------- host ----------------
extern "C" void kernel_launch(void* const* d_in, const int* in_sizes, int n_in,
                              void* d_out, int out_size)
{
    const float* x          = (const float*)d_in[0];
    const float* in_proj_w  = (const float*)d_in[1];
    const float* k_proj_w   = (const float*)d_in[2];
    const float* v_proj_w   = (const float*)d_in[3];
    const float* conv_w     = (const float*)d_in[4];
    const float* conv_b     = (const float*)d_in[5];
    const float* x_proj_w   = (const float*)d_in[6];
    const float* dt_proj_w  = (const float*)d_in[7];
    const float* dt_proj_b  = (const float*)d_in[8];
    const float* A_log      = (const float*)d_in[9];
    const float* D_skip     = (const float*)d_in[10];
    const float* dt_ln_w    = (const float*)d_in[11];
    const float* B_ln_w     = (const float*)d_in[12];
    const float* C_ln_w     = (const float*)d_in[13];
    const float* attn_ln_w  = (const float*)d_in[14];
    const float* mamba_ln_w = (const float*)d_in[15];
    const float* out_proj_w = (const float*)d_in[16];
    float* out = (float*)d_out;

    float *proj, *klin, *vlin, *ucl, *ssm, *dtn, *Bn, *Cn, *dtact;
    float *chunkh, *sumdt, *hstart, *mamba, *qr, *kr, *attn, *fused;
    cudaGetSymbolAddress((void**)&proj,   g_proj);
    cudaGetSymbolAddress((void**)&klin,   g_klin);
    cudaGetSymbolAddress((void**)&vlin,   g_vlin);
    cudaGetSymbolAddress((void**)&ucl,    g_ucl);
    cudaGetSymbolAddress((void**)&ssm,    g_ssm);
    cudaGetSymbolAddress((void**)&dtn,    g_dtn);
    cudaGetSymbolAddress((void**)&Bn,     g_Bn);
    cudaGetSymbolAddress((void**)&Cn,     g_Cn);
    cudaGetSymbolAddress((void**)&dtact,  g_dtact);
    cudaGetSymbolAddress((void**)&chunkh, g_chunkh);
    cudaGetSymbolAddress((void**)&sumdt,  g_sumdt);
    cudaGetSymbolAddress((void**)&hstart, g_hstart);
    cudaGetSymbolAddress((void**)&mamba,  g_mamba);
    cudaGetSymbolAddress((void**)&qr,     g_qr);
    cudaGetSymbolAddress((void**)&kr,     g_kr);
    cudaGetSymbolAddress((void**)&attn,   g_attn);
    cudaGetSymbolAddress((void**)&fused,  g_fused);

    // zero split-K accumulation targets (main stream)
    cudaMemsetAsync(klin, 0, (size_t)LL * 512 * sizeof(float));
    cudaMemsetAsync(vlin, 0, (size_t)LL * 512 * sizeof(float));
    cudaMemsetAsync(ssm,  0, (size_t)LL * 96 * sizeof(float));

    // projections (main stream)
    gemm_k<<<dim3(32, 16, 1), 256>>>(x, in_proj_w, proj, LL, 4096, DD, nullptr, 0, 1);
    gemm_k<<<dim3(4, 16, 4), 256>>>(x, k_proj_w, klin, LL, 512, DD, nullptr, 0, 4);
    gemm_k<<<dim3(4, 16, 4), 256>>>(x, v_proj_w, vlin, LL, 512, DD, nullptr, 0, 4);

    // ---- fork: attention branch runs on a side stream, parallel to mamba chain ----
    cudaStream_t s1;
    cudaStreamCreateWithFlags(&s1, cudaStreamNonBlocking);
    cudaEvent_t evFork, evJoin;
    cudaEventCreateWithFlags(&evFork, cudaEventDisableTiming);
    cudaEventCreateWithFlags(&evJoin, cudaEventDisableTiming);

    cudaEventRecord(evFork, 0);
    cudaStreamWaitEvent(s1, evFork, 0);

    // side stream: attention branch
    rope_q_k<<<LL * II / 256, 256, 0, s1>>>(proj, qr);
    rope_k_k<<<LL * 512 / 256, 256, 0, s1>>>(klin, kr);
    {
        size_t smem = (size_t)(3 * 8192 + 4096) * sizeof(float);
        cudaFuncSetAttribute(attn_k, cudaFuncAttributeMaxDynamicSharedMemorySize, (int)smem);
        attn_k<<<dim3(LL / 64, HQ), 256, smem, s1>>>(qr, kr, vlin, attn);
    }
    cudaEventRecord(evJoin, s1);

    // main stream: mamba branch
    conv_silu_k<<<LL * II / 256, 256>>>(proj, conv_w, conv_b, ucl);
    gemm_k<<<dim3(1, 16, 8), 256>>>(ucl, x_proj_w, ssm, LL, 96, II, nullptr, 0, 8);
    rmsnorm_dtbc_k<<<512, 128>>>(ssm, dt_ln_w, B_ln_w, C_ln_w, dtn, Bn, Cn);
    gemm_k<<<dim3(16, 16, 1), 256>>>(dtn, dt_proj_w, dtact, LL, II, TSRD, dt_proj_b, 1, 1);
    scan_passA_k<<<dim3(II / 256, NCH), 256>>>(dtact, ucl, Bn, A_log, chunkh, sumdt);
    scan_passB_k<<<(II * NST) / 256, 256>>>(chunkh, sumdt, A_log, hstart);
    scan_passC_k<<<dim3(II / 256, NCH), 256>>>(dtact, ucl, Bn, Cn, A_log, hstart,
                                               D_skip, proj, mamba);

    // join
    cudaStreamWaitEvent(0, evJoin, 0);

    // fuse + out projection (main stream)
    fuse_norm_k<<<LL, 256>>>(attn, mamba, attn_ln_w, mamba_ln_w, fused);
    gemm_k<<<dim3(8, 16, 1), 256>>>(fused, out_proj_w, out, LL, DD, II, nullptr, 0, 1);
}

// round 17
// speedup vs baseline: 1.4736x; 1.0444x over previous
#include <cuda_runtime.h>
#include <math.h>
#include <stdint.h>

// ---------------- dims ----------------
#define LL   2048
#define DD   1024
#define II   2048
#define NST  16
#define TSRD 64
#define HQ   16
#define NCH  32
#define CHSZ 64
#define EPSV 1e-6f

typedef unsigned long long u64;

// ---------------- packed f32x2 helpers ----------------
__device__ __forceinline__ u64 pack2(float lo, float hi) {
    u64 r; asm("mov.b64 %0, {%1, %2};" : "=l"(r) : "f"(lo), "f"(hi)); return r;
}
__device__ __forceinline__ float2 unpack2(u64 v) {
    float2 r; asm("mov.b64 {%0, %1}, %2;" : "=f"(r.x), "=f"(r.y) : "l"(v)); return r;
}
__device__ __forceinline__ void fma2(u64& d, u64 a, u64 b) {
    asm("fma.rn.f32x2 %0, %1, %2, %0;" : "+l"(d) : "l"(a), "l"(b));
}
__device__ __forceinline__ void mul2(u64& d, u64 a) {
    asm("mul.rn.f32x2 %0, %0, %1;" : "+l"(d) : "l"(a));
}

// ---------------- scratch ----------------
__device__ float g_proj [LL * 2 * II];
__device__ float g_klin [LL * 512];
__device__ float g_vlin [LL * 512];
__device__ float g_ucl  [LL * II];
__device__ float g_ssm  [LL * 96];
__device__ float g_dtn  [LL * TSRD];
__device__ float g_Bn   [LL * NST];
__device__ float g_Cn   [LL * NST];
__device__ float g_dtact[LL * II];
__device__ float g_chunkh[NCH * II * NST];
__device__ float g_sumdt [NCH * II];
__device__ float g_hstart[NCH * II * NST];
__device__ float g_mamba[LL * II];
__device__ float g_qr   [LL * II];
__device__ float g_kr   [LL * 512];
__device__ float g_attn [LL * II];
__device__ float g_fused[LL * II];

// ---------------- cp.async helpers ----------------
__device__ __forceinline__ void cp_async16(void* smem_dst, const void* gmem_src, int src_bytes) {
    uint32_t saddr = (uint32_t)__cvta_generic_to_shared(smem_dst);
    asm volatile("cp.async.cg.shared.global [%0], [%1], 16, %2;"
                 :: "r"(saddr), "l"(gmem_src), "r"(src_bytes));
}
__device__ __forceinline__ void cp_commit() {
    asm volatile("cp.async.commit_group;");
}
__device__ __forceinline__ void cp_wait0() {
    asm volatile("cp.async.wait_group 0;");
}

// ---------------- SGEMM: 128x128x8, 8x8/thread, cp.async DB + FFMA2 inner ----------------
// ldb/ldc: row strides of B and C. nsplit>1: K-split via blockIdx.z, atomicAdd into zeroed C.
__global__ __launch_bounds__(256) void gemm_k(
    const float* __restrict__ A, const float* __restrict__ B, float* __restrict__ C,
    int M, int N, int K, int ldb, int ldc,
    const float* __restrict__ bias, int act, int nsplit)
{
    __shared__ float As[2][8][128];
    __shared__ float Bs[2][8][128];
    const int tid = threadIdx.x;
    const int m0 = blockIdx.y * 128;
    const int n0 = blockIdx.x * 128;
    const int klen = K / nsplit;
    const int ks = blockIdx.z * klen;
    const int nk = klen / 8;
    const int tr = (tid >> 4) * 8;
    const int tc = (tid & 15) * 8;

    u64 acc2[8][4];
#pragma unroll
    for (int i = 0; i < 8; i++)
#pragma unroll
        for (int jp = 0; jp < 4; jp++) acc2[i][jp] = 0ull;

    const int la_m = tid >> 1;
    const int la_k = (tid & 1) * 4;
    const int lb_k = tid >> 5;
    const int lb_n = (tid & 31) * 4;

    const float* Ap = A + (size_t)(m0 + la_m) * K + ks + la_k;
    const int gn = n0 + lb_n;
    const float* Bp = B + (size_t)(ks + lb_k) * ldb + gn;
    int bbytes = (N - gn) * 4;
    if (bbytes < 0) bbytes = 0;
    if (bbytes > 16) bbytes = 16;

    {
        float4 av = *(const float4*)(Ap);
        As[0][la_k + 0][la_m] = av.x;
        As[0][la_k + 1][la_m] = av.y;
        As[0][la_k + 2][la_m] = av.z;
        As[0][la_k + 3][la_m] = av.w;
        if (bbytes < 16) {
            float* d = &Bs[0][lb_k][lb_n];
            d[0] = d[1] = d[2] = d[3] = 0.f;
        }
        cp_async16(&Bs[0][lb_k][lb_n], Bp, bbytes);
        cp_commit();
        cp_wait0();
    }
    __syncthreads();

    for (int kt = 0; kt < nk; kt++) {
        const int cur = kt & 1, nxt = cur ^ 1;
        const bool have = (kt + 1 < nk);
        float4 avn;
        if (have) {
            avn = *(const float4*)(Ap + (kt + 1) * 8);
            if (bbytes < 16) {
                float* d = &Bs[nxt][lb_k][lb_n];
                d[0] = d[1] = d[2] = d[3] = 0.f;
            }
            cp_async16(&Bs[nxt][lb_k][lb_n], Bp + (size_t)(kt + 1) * 8 * ldb, bbytes);
            cp_commit();
        }

#pragma unroll
        for (int kk = 0; kk < 8; kk++) {
            float a[8];
            *(float4*)&a[0] = *(const float4*)&As[cur][kk][tr];
            *(float4*)&a[4] = *(const float4*)&As[cur][kk][tr + 4];
            ulonglong2 bq0 = *(const ulonglong2*)&Bs[cur][kk][tc];
            ulonglong2 bq1 = *(const ulonglong2*)&Bs[cur][kk][tc + 4];
            u64 b2[4] = { bq0.x, bq0.y, bq1.x, bq1.y };
#pragma unroll
            for (int i = 0; i < 8; i++) {
                u64 a2 = pack2(a[i], a[i]);
#pragma unroll
                for (int jp = 0; jp < 4; jp++)
                    fma2(acc2[i][jp], a2, b2[jp]);
            }
        }

        if (have) {
            As[nxt][la_k + 0][la_m] = avn.x;
            As[nxt][la_k + 1][la_m] = avn.y;
            As[nxt][la_k + 2][la_m] = avn.z;
            As[nxt][la_k + 3][la_m] = avn.w;
            cp_wait0();
        }
        __syncthreads();
    }

#pragma unroll
    for (int i = 0; i < 8; i++) {
        int row = m0 + tr + i;
#pragma unroll
        for (int jp = 0; jp < 4; jp++) {
            float2 v2 = unpack2(acc2[i][jp]);
            float vv[2] = { v2.x, v2.y };
#pragma unroll
            for (int e = 0; e < 2; e++) {
                int col = n0 + tc + jp * 2 + e;
                if (col < N) {
                    float v = vv[e];
                    if (nsplit > 1) {
                        atomicAdd(&C[(size_t)row * ldc + col], v);
                    } else {
                        if (act == 1) {
                            float xx = v + bias[col];
                            v = fmaxf(xx, 0.f) + log1pf(__expf(-fabsf(xx)));
                        }
                        C[(size_t)row * ldc + col] = v;
                    }
                }
            }
        }
    }
}

// ---------------- conv K=4 + SiLU ----------------
__global__ __launch_bounds__(256) void conv_silu_k(
    const float* __restrict__ proj, const float* __restrict__ cw,
    const float* __restrict__ cb, float* __restrict__ ucl)
{
    int idx = blockIdx.x * 256 + threadIdx.x;
    int t = idx >> 11, i = idx & 2047;
    float4 w = *(const float4*)(cw + i * 4);
    float acc = cb[i];
    if (t >= 3) acc += proj[(size_t)(t - 3) * 4096 + i] * w.x;
    if (t >= 2) acc += proj[(size_t)(t - 2) * 4096 + i] * w.y;
    if (t >= 1) acc += proj[(size_t)(t - 1) * 4096 + i] * w.z;
    acc += proj[(size_t)t * 4096 + i] * w.w;
    ucl[idx] = acc / (1.f + __expf(-acc));
}

// ---------------- rmsnorm dt/B/C ----------------
__global__ __launch_bounds__(128) void rmsnorm_dtbc_k(
    const float* __restrict__ ssm, const float* __restrict__ wdt,
    const float* __restrict__ wB, const float* __restrict__ wC,
    float* __restrict__ dtn, float* __restrict__ Bn, float* __restrict__ Cn)
{
    int warp = (blockIdx.x * blockDim.x + threadIdx.x) >> 5;
    int lane = threadIdx.x & 31;
    if (warp >= LL) return;
    const float* row = ssm + (size_t)warp * 96;

    float v0 = row[lane], v1 = row[lane + 32];
    float ss = v0 * v0 + v1 * v1;
#pragma unroll
    for (int o = 16; o; o >>= 1) ss += __shfl_xor_sync(~0u, ss, o);
    float r = rsqrtf(ss / 64.f + EPSV);
    dtn[warp * 64 + lane]      = v0 * r * wdt[lane];
    dtn[warp * 64 + lane + 32] = v1 * r * wdt[lane + 32];

    float b = (lane < 16) ? row[64 + lane] : 0.f;
    float sb = b * b;
#pragma unroll
    for (int o = 16; o; o >>= 1) sb += __shfl_xor_sync(~0u, sb, o);
    float rb = rsqrtf(sb / 16.f + EPSV);
    if (lane < 16) Bn[warp * 16 + lane] = b * rb * wB[lane];

    float c = (lane < 16) ? row[80 + lane] : 0.f;
    float sc = c * c;
#pragma unroll
    for (int o = 16; o; o >>= 1) sc += __shfl_xor_sync(~0u, sc, o);
    float rc = rsqrtf(sc / 16.f + EPSV);
    if (lane < 16) Cn[warp * 16 + lane] = c * rc * wC[lane];
}

// ---------------- scan pass A ----------------
__global__ __launch_bounds__(256) void scan_passA_k(
    const float* __restrict__ dtact, const float* __restrict__ ucl,
    const float* __restrict__ Bn, const float* __restrict__ A_log,
    float* __restrict__ chunkh, float* __restrict__ sumdt)
{
    __shared__ float Bs[CHSZ][NST];
    const int c = blockIdx.y;
    const int i = blockIdx.x * 256 + threadIdx.x;
    for (int idx = threadIdx.x; idx < CHSZ * NST; idx += 256)
        Bs[idx >> 4][idx & 15] = Bn[(size_t)(c * CHSZ + (idx >> 4)) * NST + (idx & 15)];
    __syncthreads();

    float Ai[NST];
#pragma unroll
    for (int n = 0; n < NST; n++) Ai[n] = -__expf(A_log[(size_t)i * NST + n]);
    bool geom = true;
#pragma unroll
    for (int n = 1; n < NST; n++) {
        float ex = Ai[0] * (float)(n + 1);
        if (fabsf(Ai[n] - ex) > 1e-3f * fabsf(ex)) geom = false;
    }

    float h[NST];
#pragma unroll
    for (int n = 0; n < NST; n++) h[n] = 0.f;
    float sdt = 0.f;

    if (geom) {
        const float a0 = Ai[0];
        for (int t = 0; t < CHSZ; t++) {
            int tg = c * CHSZ + t;
            float dtv = dtact[(size_t)tg * II + i];
            float uv  = ucl[(size_t)tg * II + i];
            sdt += dtv;
            float du = dtv * uv;
            float e1 = __expf(dtv * a0);
            float p = e1;
#pragma unroll
            for (int n = 0; n < NST; n++) {
                h[n] = h[n] * p + du * Bs[t][n];
                p *= e1;
            }
        }
    } else {
        for (int t = 0; t < CHSZ; t++) {
            int tg = c * CHSZ + t;
            float dtv = dtact[(size_t)tg * II + i];
            float uv  = ucl[(size_t)tg * II + i];
            sdt += dtv;
            float du = dtv * uv;
#pragma unroll
            for (int n = 0; n < NST; n++)
                h[n] = h[n] * __expf(dtv * Ai[n]) + du * Bs[t][n];
        }
    }
#pragma unroll
    for (int n = 0; n < NST; n++)
        chunkh[((size_t)c * II + i) * NST + n] = h[n];
    sumdt[c * II + i] = sdt;
}

// ---------------- scan pass B ----------------
__global__ __launch_bounds__(256) void scan_passB_k(
    const float* __restrict__ chunkh, const float* __restrict__ sumdt,
    const float* __restrict__ A_log, float* __restrict__ hstart)
{
    int idx = blockIdx.x * 256 + threadIdx.x;
    int i = idx >> 4;
    float A = -__expf(A_log[idx]);
    float h = 0.f;
    for (int c = 0; c < NCH; c++) {
        hstart[(size_t)c * (II * NST) + idx] = h;
        h = h * __expf(A * sumdt[c * II + i]) + chunkh[(size_t)c * (II * NST) + idx];
    }
}

// ---------------- scan pass C ----------------
__global__ __launch_bounds__(256) void scan_passC_k(
    const float* __restrict__ dtact, const float* __restrict__ ucl,
    const float* __restrict__ Bn, const float* __restrict__ Cn,
    const float* __restrict__ A_log, const float* __restrict__ hstart,
    const float* __restrict__ Dsk, const float* __restrict__ proj,
    float* __restrict__ mamba)
{
    __shared__ float Bs[CHSZ][NST];
    __shared__ float Cs[CHSZ][NST];
    const int c = blockIdx.y;
    const int i = blockIdx.x * 256 + threadIdx.x;
    for (int idx = threadIdx.x; idx < CHSZ * NST; idx += 256) {
        int t = idx >> 4, n = idx & 15;
        Bs[t][n] = Bn[(size_t)(c * CHSZ + t) * NST + n];
        Cs[t][n] = Cn[(size_t)(c * CHSZ + t) * NST + n];
    }
    __syncthreads();

    float Ai[NST];
#pragma unroll
    for (int n = 0; n < NST; n++) Ai[n] = -__expf(A_log[(size_t)i * NST + n]);
    bool geom = true;
#pragma unroll
    for (int n = 1; n < NST; n++) {
        float ex = Ai[0] * (float)(n + 1);
        if (fabsf(Ai[n] - ex) > 1e-3f * fabsf(ex)) geom = false;
    }

    float h[NST];
#pragma unroll
    for (int n = 0; n < NST; n++) h[n] = hstart[((size_t)c * II + i) * NST + n];
    const float Dv = Dsk[i];

    if (geom) {
        const float a0 = Ai[0];
        for (int t = 0; t < CHSZ; t++) {
            int tg = c * CHSZ + t;
            float dtv = dtact[(size_t)tg * II + i];
            float uv  = ucl[(size_t)tg * II + i];
            float du = dtv * uv;
            float e1 = __expf(dtv * a0);
            float p = e1;
            float y = 0.f;
#pragma unroll
            for (int n = 0; n < NST; n++) {
                h[n] = h[n] * p + du * Bs[t][n];
                y += h[n] * Cs[t][n];
                p *= e1;
            }
            float g = proj[(size_t)tg * 4096 + 2048 + i];
            float sg = g / (1.f + __expf(-g));
            mamba[(size_t)tg * II + i] = (y + uv * Dv) * sg;
        }
    } else {
        for (int t = 0; t < CHSZ; t++) {
            int tg = c * CHSZ + t;
            float dtv = dtact[(size_t)tg * II + i];
            float uv  = ucl[(size_t)tg * II + i];
            float du = dtv * uv;
            float y = 0.f;
#pragma unroll
            for (int n = 0; n < NST; n++) {
                h[n] = h[n] * __expf(dtv * Ai[n]) + du * Bs[t][n];
                y += h[n] * Cs[t][n];
            }
            float g = proj[(size_t)tg * 4096 + 2048 + i];
            float sg = g / (1.f + __expf(-g));
            mamba[(size_t)tg * II + i] = (y + uv * Dv) * sg;
        }
    }
}

// ---------------- RoPE ----------------
__global__ __launch_bounds__(256) void rope_q_k(
    const float* __restrict__ proj, float* __restrict__ qr)
{
    int idx = blockIdx.x * 256 + threadIdx.x;
    int t = idx >> 11, col = idx & 2047, d = col & 127;
    int j = d & 63;
    float ang = (float)t * __expf(-(float)j * 0.14391156831212787f);
    float s, c;
    sincosf(ang, &s, &c);
    float x = proj[(size_t)t * 4096 + col];
    float other = (d < 64) ? proj[(size_t)t * 4096 + col + 64]
                           : proj[(size_t)t * 4096 + col - 64];
    qr[idx] = (d < 64) ? (x * c - other * s) : (x * c + other * s);
}

__global__ __launch_bounds__(256) void rope_k_k(
    const float* __restrict__ klin, float* __restrict__ kr)
{
    int idx = blockIdx.x * 256 + threadIdx.x;
    int t = idx >> 9, col = idx & 511, d = col & 127;
    int j = d & 63;
    float ang = (float)t * __expf(-(float)j * 0.14391156831212787f);
    float s, c;
    sincosf(ang, &s, &c);
    float x = klin[(size_t)t * 512 + col];
    float other = (d < 64) ? klin[(size_t)t * 512 + col + 64]
                           : klin[(size_t)t * 512 + col - 64];
    kr[idx] = (d < 64) ? (x * c - other * s) : (x * c + other * s);
}

// ---------------- flash attention (FFMA2 inner loops) ----------------
__global__ __launch_bounds__(256) void attn_k(
    const float* __restrict__ qr, const float* __restrict__ kr,
    const float* __restrict__ vr, float* __restrict__ attn_out)
{
    extern __shared__ float smem[];
    float* Qs = smem;
    float* Ks = Qs + 8192;
    float* Vs = Ks + 8192;
    float* Ps = Vs + 8192;
    __shared__ float m_s[64], l_s[64], al_s[64];

    const int tid = threadIdx.x;
    const int q0 = blockIdx.x * 64;
    const int h = blockIdx.y;
    const int kvh = h >> 2;
    const float scale = 0.08838834764831845f;

    for (int i = tid * 4; i < 8192; i += 1024) {
        int r = i >> 7, d = i & 127;
        float4 q = *(const float4*)(qr + (size_t)(q0 + r) * 2048 + h * 128 + d);
        q.x *= scale; q.y *= scale; q.z *= scale; q.w *= scale;
        *(float4*)&Qs[i] = q;
    }
    if (tid < 64) { m_s[tid] = -1e30f; l_s[tid] = 0.f; al_s[tid] = 1.f; }

    const int sr = (tid >> 4) << 2;
    const int sc = (tid & 15) << 2;
    const int pc = (tid & 15) << 3;
    u64 O2[4][4];
#pragma unroll
    for (int i = 0; i < 4; i++)
#pragma unroll
        for (int jp = 0; jp < 4; jp++) O2[i][jp] = 0ull;

    __syncthreads();

    int wstart = q0 - 1024; if (wstart < 128) wstart = 128;

    for (int ti = 0; ti < 20; ti++) {
        int k0;
        if (ti < 2) { k0 = ti << 6; }
        else { k0 = wstart + ((ti - 2) << 6); if (k0 > q0) break; }

        for (int i = tid * 4; i < 8192; i += 1024) {
            int r = i >> 7, d = i & 127;
            size_t off = (size_t)(k0 + r) * 512 + kvh * 128 + d;
            *(float4*)&Ks[i] = *(const float4*)(kr + off);
            *(float4*)&Vs[i] = *(const float4*)(vr + off);
        }
        __syncthreads();

        u64 s2[4][4];
#pragma unroll
        for (int i = 0; i < 4; i++)
#pragma unroll
            for (int j = 0; j < 4; j++) s2[i][j] = 0ull;

        for (int kk = 0; kk < 128; kk += 4) {
            ulonglong2 a2[4], b2[4];
#pragma unroll
            for (int i = 0; i < 4; i++) a2[i] = *(const ulonglong2*)&Qs[(sr + i) * 128 + kk];
#pragma unroll
            for (int j = 0; j < 4; j++) b2[j] = *(const ulonglong2*)&Ks[(sc + j) * 128 + kk];
#pragma unroll
            for (int i = 0; i < 4; i++)
#pragma unroll
                for (int j = 0; j < 4; j++) {
                    fma2(s2[i][j], a2[i].x, b2[j].x);
                    fma2(s2[i][j], a2[i].y, b2[j].y);
                }
        }

        float s[4][4];
#pragma unroll
        for (int i = 0; i < 4; i++)
#pragma unroll
            for (int j = 0; j < 4; j++) {
                float2 t2 = unpack2(s2[i][j]);
                s[i][j] = t2.x + t2.y;
            }

#pragma unroll
        for (int i = 0; i < 4; i++) {
            int qi = q0 + sr + i;
#pragma unroll
            for (int j = 0; j < 4; j++) {
                int ki = k0 + sc + j;
                bool ok = (ki <= qi) && (((qi - ki) <= 1024) || (ki < 128));
                if (!ok) s[i][j] = -1e30f;
            }
        }

        float rmax[4];
#pragma unroll
        for (int i = 0; i < 4; i++)
            rmax[i] = fmaxf(fmaxf(s[i][0], s[i][1]), fmaxf(s[i][2], s[i][3]));
#pragma unroll
        for (int o = 1; o < 16; o <<= 1)
#pragma unroll
            for (int i = 0; i < 4; i++)
                rmax[i] = fmaxf(rmax[i], __shfl_xor_sync(~0u, rmax[i], o));

        float mo[4], mn[4], rs[4];
#pragma unroll
        for (int i = 0; i < 4; i++) {
            mo[i] = m_s[sr + i];
            mn[i] = fmaxf(mo[i], rmax[i]);
            rs[i] = 0.f;
        }
#pragma unroll
        for (int i = 0; i < 4; i++)
#pragma unroll
            for (int j = 0; j < 4; j++) {
                float p = __expf(s[i][j] - mn[i]);
                Ps[(sr + i) * 64 + sc + j] = p;
                rs[i] += p;
            }
#pragma unroll
        for (int o = 1; o < 16; o <<= 1)
#pragma unroll
            for (int i = 0; i < 4; i++)
                rs[i] += __shfl_xor_sync(~0u, rs[i], o);

        if ((tid & 15) == 0) {
#pragma unroll
            for (int i = 0; i < 4; i++) {
                float al = __expf(mo[i] - mn[i]);
                al_s[sr + i] = al;
                l_s[sr + i] = l_s[sr + i] * al + rs[i];
                m_s[sr + i] = mn[i];
            }
        }
        __syncthreads();

#pragma unroll
        for (int i = 0; i < 4; i++) {
            u64 al2 = pack2(al_s[sr + i], al_s[sr + i]);
#pragma unroll
            for (int jp = 0; jp < 4; jp++) mul2(O2[i][jp], al2);
        }

        for (int cix = 0; cix < 64; cix++) {
            ulonglong2 v0 = *(const ulonglong2*)&Vs[cix * 128 + pc];
            ulonglong2 v1 = *(const ulonglong2*)&Vs[cix * 128 + pc + 4];
#pragma unroll
            for (int i = 0; i < 4; i++) {
                float p = Ps[(sr + i) * 64 + cix];
                u64 p2 = pack2(p, p);
                fma2(O2[i][0], p2, v0.x);
                fma2(O2[i][1], p2, v0.y);
                fma2(O2[i][2], p2, v1.x);
                fma2(O2[i][3], p2, v1.y);
            }
        }
        __syncthreads();
    }

#pragma unroll
    for (int i = 0; i < 4; i++) {
        float inv = 1.f / l_s[sr + i];
        float2 o0 = unpack2(O2[i][0]);
        float2 o1 = unpack2(O2[i][1]);
        float2 o2 = unpack2(O2[i][2]);
        float2 o3 = unpack2(O2[i][3]);
        float4 w0 = make_float4(o0.x * inv, o0.y * inv, o1.x * inv, o1.y * inv);
        float4 w1 = make_float4(o2.x * inv, o2.y * inv, o3.x * inv, o3.y * inv);
        float* dst = attn_out + (size_t)(q0 + sr + i) * 2048 + h * 128 + pc;
        *(float4*)dst = w0;
        *(float4*)(dst + 4) = w1;
    }
}

// ---------------- fuse norms ----------------
__global__ __launch_bounds__(256) void fuse_norm_k(
    const float* __restrict__ attn, const float* __restrict__ mamba,
    const float* __restrict__ wa, const float* __restrict__ wm,
    float* __restrict__ fused)
{
    __shared__ float sh[18];
    int t = blockIdx.x, tid = threadIdx.x;
    float av[8], mv[8];
    float sa = 0.f, sm = 0.f;
#pragma unroll
    for (int k = 0; k < 8; k++) {
        int col = tid + k * 256;
        av[k] = attn[(size_t)t * II + col];
        mv[k] = mamba[(size_t)t * II + col];
        sa += av[k] * av[k];
        sm += mv[k] * mv[k];
    }
#pragma unroll
    for (int o = 16; o; o >>= 1) {
        sa += __shfl_xor_sync(~0u, sa, o);
        sm += __shfl_xor_sync(~0u, sm, o);
    }
    int w = tid >> 5;
    if ((tid & 31) == 0) { sh[w] = sa; sh[8 + w] = sm; }
    __syncthreads();
    if (tid == 0) {
        float ta = 0.f, tm = 0.f;
        for (int k = 0; k < 8; k++) { ta += sh[k]; tm += sh[8 + k]; }
        sh[16] = ta; sh[17] = tm;
    }
    __syncthreads();
    float ra = rsqrtf(sh[16] / (float)II + EPSV);
    float rm = rsqrtf(sh[17] / (float)II + EPSV);
#pragma unroll
    for (int k = 0; k < 8; k++) {
        int col = tid + k * 256;
        fused[(size_t)t * II + col] = 0.5f * (av[k] * ra * wa[col] + mv[k] * rm * wm[col]);
    }
}

// ---------------- host ----------------
extern "C" void kernel_launch(void* const* d_in, const int* in_sizes, int n_in,
                              void* d_out, int out_size)
{
    const float* x          = (const float*)d_in[0];
    const float* in_proj_w  = (const float*)d_in[1];
    const float* k_proj_w   = (const float*)d_in[2];
    const float* v_proj_w   = (const float*)d_in[3];
    const float* conv_w     = (const float*)d_in[4];
    const float* conv_b     = (const float*)d_in[5];
    const float* x_proj_w   = (const float*)d_in[6];
    const float* dt_proj_w  = (const float*)d_in[7];
    const float* dt_proj_b  = (const float*)d_in[8];
    const float* A_log      = (const float*)d_in[9];
    const float* D_skip     = (const float*)d_in[10];
    const float* dt_ln_w    = (const float*)d_in[11];
    const float* B_ln_w     = (const float*)d_in[12];
    const float* C_ln_w     = (const float*)d_in[13];
    const float* attn_ln_w  = (const float*)d_in[14];
    const float* mamba_ln_w = (const float*)d_in[15];
    const float* out_proj_w = (const float*)d_in[16];
    float* out = (float*)d_out;

    float *proj, *klin, *vlin, *ucl, *ssm, *dtn, *Bn, *Cn, *dtact;
    float *chunkh, *sumdt, *hstart, *mamba, *qr, *kr, *attn, *fused;
    cudaGetSymbolAddress((void**)&proj,   g_proj);
    cudaGetSymbolAddress((void**)&klin,   g_klin);
    cudaGetSymbolAddress((void**)&vlin,   g_vlin);
    cudaGetSymbolAddress((void**)&ucl,    g_ucl);
    cudaGetSymbolAddress((void**)&ssm,    g_ssm);
    cudaGetSymbolAddress((void**)&dtn,    g_dtn);
    cudaGetSymbolAddress((void**)&Bn,     g_Bn);
    cudaGetSymbolAddress((void**)&Cn,     g_Cn);
    cudaGetSymbolAddress((void**)&dtact,  g_dtact);
    cudaGetSymbolAddress((void**)&chunkh, g_chunkh);
    cudaGetSymbolAddress((void**)&sumdt,  g_sumdt);
    cudaGetSymbolAddress((void**)&hstart, g_hstart);
    cudaGetSymbolAddress((void**)&mamba,  g_mamba);
    cudaGetSymbolAddress((void**)&qr,     g_qr);
    cudaGetSymbolAddress((void**)&kr,     g_kr);
    cudaGetSymbolAddress((void**)&attn,   g_attn);
    cudaGetSymbolAddress((void**)&fused,  g_fused);

    // ONE side stream (R11-proven harness-safe footprint)
    cudaStream_t s1;
    cudaStreamCreateWithFlags(&s1, cudaStreamNonBlocking);
    cudaEvent_t evFork, evLat, evJoin;
    cudaEventCreateWithFlags(&evFork, cudaEventDisableTiming);
    cudaEventCreateWithFlags(&evLat,  cudaEventDisableTiming);
    cudaEventCreateWithFlags(&evJoin, cudaEventDisableTiming);

    size_t smem = (size_t)(3 * 8192 + 4096) * sizeof(float);
    cudaFuncSetAttribute(attn_k, cudaFuncAttributeMaxDynamicSharedMemorySize, (int)smem);

    // fork at t=0
    cudaEventRecord(evFork, 0);
    cudaStreamWaitEvent(s1, evFork, 0);

    // s1: kv branch (independent of in_proj) — overlaps the latent GEMM
    cudaMemsetAsync(klin, 0, (size_t)LL * 512 * sizeof(float), s1);
    cudaMemsetAsync(vlin, 0, (size_t)LL * 512 * sizeof(float), s1);
    gemm_k<<<dim3(4, 16, 4), 256, 0, s1>>>(x, k_proj_w, klin, LL, 512, DD, 512, 512, nullptr, 0, 4);
    gemm_k<<<dim3(4, 16, 4), 256, 0, s1>>>(x, v_proj_w, vlin, LL, 512, DD, 512, 512, nullptr, 0, 4);
    rope_k_k<<<LL * 512 / 256, 256, 0, s1>>>(klin, kr);

    // main: latent half of in_proj (serial prefix)
    cudaMemsetAsync(ssm, 0, (size_t)LL * 96 * sizeof(float));
    gemm_k<<<dim3(16, 16, 1), 256>>>(x, in_proj_w, proj, LL, 2048, DD, 4096, 4096, nullptr, 0, 1);
    cudaEventRecord(evLat, 0);

    // s1: attention branch once latent is ready
    cudaStreamWaitEvent(s1, evLat, 0);
    rope_q_k<<<LL * II / 256, 256, 0, s1>>>(proj, qr);
    attn_k<<<dim3(LL / 64, HQ), 256, smem, s1>>>(qr, kr, vlin, attn);
    cudaEventRecord(evJoin, s1);

    // main: gate half of in_proj (program-order before scan passC), then mamba chain
    gemm_k<<<dim3(16, 16, 1), 256>>>(x, in_proj_w + 2048, proj + 2048, LL, 2048, DD, 4096, 4096, nullptr, 0, 1);
    conv_silu_k<<<LL * II / 256, 256>>>(proj, conv_w, conv_b, ucl);
    gemm_k<<<dim3(1, 16, 8), 256>>>(ucl, x_proj_w, ssm, LL, 96, II, 96, 96, nullptr, 0, 8);
    rmsnorm_dtbc_k<<<512, 128>>>(ssm, dt_ln_w, B_ln_w, C_ln_w, dtn, Bn, Cn);
    gemm_k<<<dim3(16, 16, 1), 256>>>(dtn, dt_proj_w, dtact, LL, II, TSRD, II, II, dt_proj_b, 1, 1);
    scan_passA_k<<<dim3(II / 256, NCH), 256>>>(dtact, ucl, Bn, A_log, chunkh, sumdt);
    scan_passB_k<<<(II * NST) / 256, 256>>>(chunkh, sumdt, A_log, hstart);
    scan_passC_k<<<dim3(II / 256, NCH), 256>>>(dtact, ucl, Bn, Cn, A_log, hstart,
                                               D_skip, proj, mamba);

    // join attention
    cudaStreamWaitEvent(0, evJoin, 0);

    // fuse + out projection
    fuse_norm_k<<<LL, 256>>>(attn, mamba, attn_ln_w, mamba_ln_w, fused);
    gemm_k<<<dim3(8, 16, 1), 256>>>(fused, out_proj_w, out, LL, DD, II, DD, DD, nullptr, 0, 1);
}